// round 6
// baseline (speedup 1.0000x reference)
#include <cuda_runtime.h>
#include <cuda_fp16.h>
#include <cstdint>
#include <math.h>

#define B_ 4
#define T_ 2048
#define C_ 1024
#define H_ 16
#define D_ 64
#define R_ 64
#define NT 8192   // B*T

// ---------------- scratch (device globals; no allocation) ----------------
__device__ __half g_xh[NT * C_];      // x converted to half
__device__ __half g_W[256 * 1024];    // stacked scaled V-weights (half)
__device__ __half g_Wu[4 * 1024 * 64];// U weights (half)
__device__ __half g_P[NT * 192];      // rank-space P for q,k,v
__device__ __half g_P2[NT * 64];      // rank-space P for c-proj
__device__ __half g_Qh[NT * C_];      // [B,H,T,D], pre-scaled by 0.125*log2e
__device__ __half g_Kh[NT * C_];
__device__ __half g_Vh[NT * C_];
__device__ __half g_Yh[NT * C_];      // attention out [B,T,C]

// =================== portable tensor-core helpers (sm_80+) =================
__device__ __forceinline__ float ex2(float x) {
    float y;
    asm("ex2.approx.f32 %0, %1;" : "=f"(y) : "f"(x));
    return y;
}
__device__ __forceinline__ void mma_f16(float* d, const uint32_t* a,
                                        uint32_t b0, uint32_t b1) {
    asm volatile(
        "mma.sync.aligned.m16n8k16.row.col.f32.f16.f16.f32 "
        "{%0,%1,%2,%3}, {%4,%5,%6,%7}, {%8,%9}, {%0,%1,%2,%3};"
        : "+f"(d[0]), "+f"(d[1]), "+f"(d[2]), "+f"(d[3])
        : "r"(a[0]), "r"(a[1]), "r"(a[2]), "r"(a[3]), "r"(b0), "r"(b1));
}
__device__ __forceinline__ uint32_t smem_u32(const void* p) {
    uint32_t a;
    asm("{ .reg .u64 t; cvta.to.shared.u64 t, %1; cvt.u32.u64 %0, t; }"
        : "=r"(a) : "l"(p));
    return a;
}
__device__ __forceinline__ void cp16(uint32_t dst, const void* src) {
    asm volatile("cp.async.cg.shared.global [%0], [%1], 16;"
                 :: "r"(dst), "l"(src));
}
#define CP_COMMIT() asm volatile("cp.async.commit_group;" ::: "memory")
#define CP_WAIT(n)  asm volatile("cp.async.wait_group %0;" :: "n"(n) : "memory")
#define LDSM4(r, a)                                                         \
    asm volatile("ldmatrix.sync.aligned.m8n8.x4.shared.b16 "                \
                 "{%0,%1,%2,%3}, [%4];"                                     \
                 : "=r"((r)[0]), "=r"((r)[1]), "=r"((r)[2]), "=r"((r)[3])   \
                 : "r"(a))
#define LDSM4T(r, a)                                                        \
    asm volatile("ldmatrix.sync.aligned.m8n8.x4.trans.shared.b16 "          \
                 "{%0,%1,%2,%3}, [%4];"                                     \
                 : "=r"((r)[0]), "=r"((r)[1]), "=r"((r)[2]), "=r"((r)[3])   \
                 : "r"(a))
__device__ __forceinline__ uint32_t pack_h2(float lo, float hi) {
    __half2 h = __floats2half2_rn(lo, hi);
    return *(uint32_t*)&h;
}

// ---------------------------------------------------------------------------
// K_cvt: x fp32 -> half
// ---------------------------------------------------------------------------
__global__ __launch_bounds__(256) void k_cvt(const float* __restrict__ x) {
    const int base = (blockIdx.x * 256 + threadIdx.x) * 16;
    #pragma unroll
    for (int g = 0; g < 4; g++) {
        float4 v = *(const float4*)(x + base + g * 4);
        *(__half2*)(g_xh + base + g * 4)     = __floats2half2_rn(v.x, v.y);
        *(__half2*)(g_xh + base + g * 4 + 2) = __floats2half2_rn(v.z, v.w);
    }
}

// ---------------------------------------------------------------------------
// K_prepW: W rows [0,64) Vq*s*0.125*log2e, [64,128) Vk*s, [128,192) Vv*s,
//          [192,256) Vc*s.
// ---------------------------------------------------------------------------
__global__ __launch_bounds__(256) void k_prepW(
    const float* __restrict__ qV, const float* __restrict__ kV,
    const float* __restrict__ vV, const float* __restrict__ cV) {
    const int b = blockIdx.x, tid = threadIdx.x;
    const int grp = b >> 6, r = b & 63;
    const float* Vsrc = (grp == 0) ? qV : (grp == 1) ? kV
                      : (grp == 2) ? vV : cV;
    float sc = powf((float)(r + 1), -0.7f);
    if (grp == 0) sc *= 0.125f * 1.4426950408889634f;
    const int c = tid * 4;
    float4 v = *(const float4*)(Vsrc + (size_t)r * 1024 + c);
    *(__half2*)(g_W + (size_t)b * 1024 + c)     = __floats2half2_rn(v.x * sc, v.y * sc);
    *(__half2*)(g_W + (size_t)b * 1024 + c + 2) = __floats2half2_rn(v.z * sc, v.w * sc);
}

// K_prepU: cvt qU,kU,vU,cU -> g_Wu (half)
__global__ __launch_bounds__(256) void k_prepU(
    const float* __restrict__ qU, const float* __restrict__ kU,
    const float* __restrict__ vU, const float* __restrict__ cU) {
    const float* Us[4] = {qU, kU, vU, cU};
    const int base = blockIdx.x * 1024 + threadIdx.x * 4;
    const int w = base >> 16, off = base & 65535;
    float4 u = *(const float4*)(Us[w] + off);
    *(__half2*)(g_Wu + base)     = __floats2half2_rn(u.x, u.y);
    *(__half2*)(g_Wu + base + 2) = __floats2half2_rn(u.z, u.w);
}

// ---------------------------------------------------------------------------
// K1: stage-1 GEMM  P[m, grp*64+n] = A[m,:1024] @ W[wrow0+grp*64+n, :1024]^T
// grid (NT/64, ngroups).  64 rows x 64 cols per CTA, 8 warps (2m x 4n),
// 3-stage cp.async pipeline over K-chunks of 32.
// ---------------------------------------------------------------------------
#define PADH1 40   // halfs; 80B row stride
__global__ __launch_bounds__(256) void k_g1(const __half* __restrict__ A,
                                            int wrow0, int ps,
                                            __half* __restrict__ Pout) {
    extern __shared__ __half sg1h[];
    const int tid = threadIdx.x, w = tid >> 5, lane = tid & 31;
    const int quad = lane >> 2, qc = lane & 3;
    const int wm = w & 1, wn = w >> 1;
    const int m0 = blockIdx.x * 64;
    const int grp = blockIdx.y;
    const __half* Wp = g_W + (size_t)(wrow0 + grp * 64) * 1024;

    auto Abuf = [&](int s) { return sg1h + s * 2 * 64 * PADH1; };
    auto Bbuf = [&](int s) { return sg1h + s * 2 * 64 * PADH1 + 64 * PADH1; };

    auto stage = [&](int ch, int s) {
        const int k0 = ch * 32;
        const int r = tid >> 2, c8 = (tid & 3) * 8;
        cp16(smem_u32(Abuf(s) + r * PADH1 + c8),
             A + (size_t)(m0 + r) * 1024 + k0 + c8);
        cp16(smem_u32(Bbuf(s) + r * PADH1 + c8),
             Wp + (size_t)r * 1024 + k0 + c8);
    };

    float acc[2][2][4] = {};
    stage(0, 0); CP_COMMIT();
    stage(1, 1); CP_COMMIT();

    for (int ch = 0; ch < 32; ch++) {
        if (ch + 2 < 32) stage(ch + 2, (ch + 2) % 3);
        CP_COMMIT();
        CP_WAIT(2);
        __syncthreads();
        const __half* Ab = Abuf(ch % 3);
        const __half* Bb = Bbuf(ch % 3);
        #pragma unroll
        for (int kb = 0; kb < 2; kb++) {
            uint32_t a[2][4];
            #pragma unroll
            for (int mf = 0; mf < 2; mf++) {
                const __half* ap = Ab + (wm * 32 + mf * 16 + quad) * PADH1
                                 + kb * 16 + 2 * qc;
                a[mf][0] = *(const uint32_t*)(ap);
                a[mf][1] = *(const uint32_t*)(ap + 8 * PADH1);
                a[mf][2] = *(const uint32_t*)(ap + 8);
                a[mf][3] = *(const uint32_t*)(ap + 8 * PADH1 + 8);
            }
            #pragma unroll
            for (int nb = 0; nb < 2; nb++) {
                const __half* bp = Bb + (wn * 16 + nb * 8 + quad) * PADH1
                                 + kb * 16 + 2 * qc;
                uint32_t b0 = *(const uint32_t*)(bp);
                uint32_t b1 = *(const uint32_t*)(bp + 8);
                mma_f16(acc[0][nb], a[0], b0, b1);
                mma_f16(acc[1][nb], a[1], b0, b1);
            }
        }
        __syncthreads();
    }

    #pragma unroll
    for (int mf = 0; mf < 2; mf++) {
        const int row = m0 + wm * 32 + mf * 16 + quad;
        #pragma unroll
        for (int nb = 0; nb < 2; nb++) {
            const int col = grp * 64 + wn * 16 + nb * 8 + 2 * qc;
            *(__half2*)(Pout + (size_t)row * ps + col) =
                __floats2half2_rn(acc[mf][nb][0], acc[mf][nb][1]);
            *(__half2*)(Pout + (size_t)(row + 8) * ps + col) =
                __floats2half2_rn(acc[mf][nb][2], acc[mf][nb][3]);
        }
    }
}

// ---------------------------------------------------------------------------
// K2: stage-2 GEMM  y[m,n] = P[m,:64] @ U[n0+n,:64]^T   (fp16 mma)
// M-tile 128 (8 warps x 16 rows), N-tile 128, K=64 (kb<4).
// mode 0: grid.z=3 -> q/k/v head-split half. mode 1: c-proj -> fp32 out.
// ---------------------------------------------------------------------------
#define PADH2 72   // halfs; 144B row stride
__global__ __launch_bounds__(256) void k_g2(const __half* __restrict__ Pbase,
                                            int ps,
                                            const __half* __restrict__ Wubase,
                                            int mode, float* __restrict__ outp) {
    extern __shared__ __half sg2h[];
    __half* As = sg2h;                 // [128][PADH2]
    __half* Bs = sg2h + 128 * PADH2;   // [128][PADH2]
    const int tid = threadIdx.x, w = tid >> 5, lane = tid & 31;
    const int quad = lane >> 2, qc = lane & 3;
    const int m0 = blockIdx.y * 128, n0 = blockIdx.x * 128;
    const int z = blockIdx.z;
    const __half* Pin = Pbase + (mode == 0 ? z * 64 : 0);
    const __half* Wu  = Wubase + (mode == 0 ? z * 65536 : 0);

    #pragma unroll
    for (int t = 0; t < 4; t++) {       // A: 1024 cp16
        int idx = tid + t * 256;
        int r = idx >> 3, c8 = (idx & 7) * 8;
        cp16(smem_u32(As + r * PADH2 + c8),
             Pin + (size_t)(m0 + r) * ps + c8);
    }
    #pragma unroll
    for (int t = 0; t < 4; t++) {       // B: 1024 cp16
        int idx = tid + t * 256;
        int n = idx >> 3, c8 = (idx & 7) * 8;
        cp16(smem_u32(Bs + n * PADH2 + c8),
             Wu + (size_t)(n0 + n) * 64 + c8);
    }
    CP_COMMIT();
    CP_WAIT(0);
    __syncthreads();

    float acc[16][4];
    #pragma unroll
    for (int nb = 0; nb < 16; nb++)
        #pragma unroll
        for (int i = 0; i < 4; i++) acc[nb][i] = 0.f;

    #pragma unroll
    for (int kb = 0; kb < 4; kb++) {
        uint32_t a[4];
        const __half* ap = As + (w * 16 + quad) * PADH2 + kb * 16 + 2 * qc;
        a[0] = *(const uint32_t*)(ap);
        a[1] = *(const uint32_t*)(ap + 8 * PADH2);
        a[2] = *(const uint32_t*)(ap + 8);
        a[3] = *(const uint32_t*)(ap + 8 * PADH2 + 8);
        #pragma unroll
        for (int nb = 0; nb < 16; nb++) {
            const __half* bp = Bs + (nb * 8 + quad) * PADH2 + kb * 16 + 2 * qc;
            mma_f16(acc[nb], a, *(const uint32_t*)(bp),
                    *(const uint32_t*)(bp + 8));
        }
    }

    const int row = m0 + w * 16 + quad;
    if (mode == 0) {
        __half* dst = (z == 0) ? g_Qh : (z == 1) ? g_Kh : g_Vh;
        const int b = row >> 11, t = row & (T_ - 1);
        #pragma unroll
        for (int nb = 0; nb < 16; nb++) {
            const int col = n0 + nb * 8 + 2 * qc;
            const int h = col >> 6, d = col & 63;
            __half* p0 = dst + (((size_t)(b * H_ + h) * T_ + t) * D_) + d;
            *(__half2*)p0 = __floats2half2_rn(acc[nb][0], acc[nb][1]);
            *(__half2*)(p0 + 8 * D_) = __floats2half2_rn(acc[nb][2], acc[nb][3]);
        }
    } else {
        #pragma unroll
        for (int nb = 0; nb < 16; nb++) {
            const int col = n0 + nb * 8 + 2 * qc;
            float* p0 = outp + (size_t)row * C_ + col;
            *(float2*)p0 = make_float2(acc[nb][0], acc[nb][1]);
            *(float2*)(p0 + 8 * C_) = make_float2(acc[nb][2], acc[nb][3]);
        }
    }
}

// ---------------------------------------------------------------------------
// K3: causal flash attention, fp16 mma + ldmatrix.
// 256 q-rows/CTA, 8 warps x 32 rows (2 m-frags share every K/V b-frag),
// 64-key tiles, cp.async double buffer. P stays in registers (S C-frag ==
// P A-frag layout). No online max (|S| << 1); normalize once at the end.
// ---------------------------------------------------------------------------
#define PADA 72    // halfs; 144B stride
__global__ __launch_bounds__(256) void k_attn() {
    extern __shared__ __half sah[];
    __half* Qs  = sah;                      // [256][PADA]
    __half* Ksb = sah + 256 * PADA;         // [2][64][PADA]
    __half* Vsb = Ksb + 2 * 64 * PADA;      // [2][64][PADA]
    const int tid = threadIdx.x, w = tid >> 5, lane = tid & 31;
    const int quad = lane >> 2, qc = lane & 3;
    const int msel = lane >> 3, rsel = lane & 7;
    const int mrow_a = (msel & 1) * 8 + rsel;   // Q / V(trans) row part
    const int mcol_a = (msel >> 1) * 8;
    const int mrow_b = (msel >> 1) * 8 + rsel;  // K row part
    const int mcol_b = (msel & 1) * 8;
    const int bh = blockIdx.y;
    const int qt = gridDim.x - 1 - blockIdx.x;  // heavy tiles first
    const int q0 = qt * 256;
    const __half* Qb = g_Qh + (size_t)bh * T_ * D_;
    const __half* Kb = g_Kh + (size_t)bh * T_ * D_;
    const __half* Vb = g_Vh + (size_t)bh * T_ * D_;
    const int nt = 4 * qt + 4;

    auto stage = [&](int j, int buf) {
        const __half* Kt = Kb + (size_t)j * 64 * D_;
        const __half* Vt = Vb + (size_t)j * 64 * D_;
        __half* Kd = Ksb + buf * 64 * PADA;
        __half* Vd = Vsb + buf * 64 * PADA;
        #pragma unroll
        for (int t = 0; t < 2; t++) {
            int idx = tid + t * 256;
            int r = idx >> 3, c8 = (idx & 7) * 8;
            cp16(smem_u32(Kd + r * PADA + c8), Kt + (size_t)r * D_ + c8);
            cp16(smem_u32(Vd + r * PADA + c8), Vt + (size_t)r * D_ + c8);
        }
    };

    // Q tile (256 rows) + first K/V tile
    #pragma unroll
    for (int t = 0; t < 8; t++) {
        int idx = tid + t * 256;
        int r = idx >> 3, c8 = (idx & 7) * 8;
        cp16(smem_u32(Qs + r * PADA + c8), Qb + (size_t)(q0 + r) * D_ + c8);
    }
    stage(0, 0);
    CP_COMMIT();

    uint32_t qa[2][4][4];
    float o[2][8][4] = {};
    float lsum[2][2] = {};
    int buf = 0;

    for (int j = 0; j < nt; j++) {
        if (j + 1 < nt) { stage(j + 1, buf ^ 1); CP_COMMIT(); CP_WAIT(1); }
        else            { CP_WAIT(0); }
        __syncthreads();
        const __half* Ks = Ksb + buf * 64 * PADA;
        const __half* Vs = Vsb + buf * 64 * PADA;

        if (j == 0) {        // Q a-frags once (Qs complete after first wait)
            #pragma unroll
            for (int mf = 0; mf < 2; mf++)
                #pragma unroll
                for (int kb = 0; kb < 4; kb++)
                    LDSM4(qa[mf][kb],
                          smem_u32(Qs + (w * 32 + mf * 16 + mrow_a) * PADA
                                   + kb * 16 + mcol_a));
        }

        // ---- S = Q @ K^T : 32x64 per warp ----
        float s[2][8][4];
        #pragma unroll
        for (int mf = 0; mf < 2; mf++)
            #pragma unroll
            for (int nb = 0; nb < 8; nb++)
                #pragma unroll
                for (int i = 0; i < 4; i++) s[mf][nb][i] = 0.f;
        #pragma unroll
        for (int kb = 0; kb < 4; kb++)
            #pragma unroll
            for (int nbp = 0; nbp < 4; nbp++) {
                uint32_t bf[4];
                LDSM4(bf, smem_u32(Ks + (nbp * 16 + mrow_b) * PADA
                                   + kb * 16 + mcol_b));
                #pragma unroll
                for (int mf = 0; mf < 2; mf++) {
                    mma_f16(s[mf][2 * nbp],     qa[mf][kb], bf[0], bf[1]);
                    mma_f16(s[mf][2 * nbp + 1], qa[mf][kb], bf[2], bf[3]);
                }
            }

        // ---- softmax (no max-shift; log2e folded into Q) ----
        const bool maskt = (j >= nt - 4);
        #pragma unroll
        for (int mf = 0; mf < 2; mf++) {
            const int rowrel0 = q0 + w * 32 + mf * 16 + quad - 64 * j;
            #pragma unroll
            for (int nb = 0; nb < 8; nb++) {
                const int k0 = nb * 8 + 2 * qc;
                float p0 = ex2(s[mf][nb][0]), p1 = ex2(s[mf][nb][1]);
                float p2 = ex2(s[mf][nb][2]), p3 = ex2(s[mf][nb][3]);
                if (maskt) {
                    if (k0 > rowrel0)         p0 = 0.f;
                    if (k0 + 1 > rowrel0)     p1 = 0.f;
                    if (k0 > rowrel0 + 8)     p2 = 0.f;
                    if (k0 + 1 > rowrel0 + 8) p3 = 0.f;
                }
                lsum[mf][0] += p0 + p1;
                lsum[mf][1] += p2 + p3;
                s[mf][nb][0] = p0; s[mf][nb][1] = p1;
                s[mf][nb][2] = p2; s[mf][nb][3] = p3;
            }
        }

        // ---- O += P @ V  (P A-frags direct from C-frags) ----
        #pragma unroll
        for (int kb = 0; kb < 4; kb++) {
            uint32_t pa[2][4];
            #pragma unroll
            for (int mf = 0; mf < 2; mf++) {
                pa[mf][0] = pack_h2(s[mf][2 * kb][0],     s[mf][2 * kb][1]);
                pa[mf][1] = pack_h2(s[mf][2 * kb][2],     s[mf][2 * kb][3]);
                pa[mf][2] = pack_h2(s[mf][2 * kb + 1][0], s[mf][2 * kb + 1][1]);
                pa[mf][3] = pack_h2(s[mf][2 * kb + 1][2], s[mf][2 * kb + 1][3]);
            }
            #pragma unroll
            for (int nbp = 0; nbp < 4; nbp++) {
                uint32_t vf[4];
                LDSM4T(vf, smem_u32(Vs + (kb * 16 + mrow_a) * PADA
                                    + nbp * 16 + mcol_a));
                #pragma unroll
                for (int mf = 0; mf < 2; mf++) {
                    mma_f16(o[mf][2 * nbp],     pa[mf], vf[0], vf[1]);
                    mma_f16(o[mf][2 * nbp + 1], pa[mf], vf[2], vf[3]);
                }
            }
        }
        __syncthreads();
        buf ^= 1;
    }

    // ---- epilogue: reduce row-sums over the 4 lanes of each row ----
    #pragma unroll
    for (int mf = 0; mf < 2; mf++)
        #pragma unroll
        for (int hh = 0; hh < 2; hh++) {
            lsum[mf][hh] += __shfl_xor_sync(0xffffffffu, lsum[mf][hh], 1);
            lsum[mf][hh] += __shfl_xor_sync(0xffffffffu, lsum[mf][hh], 2);
        }

    const int b = bh >> 4, h = bh & 15;
    #pragma unroll
    for (int mf = 0; mf < 2; mf++) {
        const float inv0 = 1.f / lsum[mf][0], inv1 = 1.f / lsum[mf][1];
        const int r0 = q0 + w * 32 + mf * 16 + quad;
        __half* y0 = g_Yh + ((size_t)b * T_ + r0) * C_ + h * 64;
        __half* y1 = y0 + 8 * C_;
        #pragma unroll
        for (int nb = 0; nb < 8; nb++) {
            const int c = nb * 8 + 2 * qc;
            *(__half2*)(y0 + c) = __floats2half2_rn(o[mf][nb][0] * inv0,
                                                    o[mf][nb][1] * inv0);
            *(__half2*)(y1 + c) = __floats2half2_rn(o[mf][nb][2] * inv1,
                                                    o[mf][nb][3] * inv1);
        }
    }
}

// ---------------------------------------------------------------------------
extern "C" void kernel_launch(void* const* d_in, const int* in_sizes, int n_in,
                              void* d_out, int out_size) {
    (void)in_sizes; (void)n_in; (void)out_size;
    const float* x  = (const float*)d_in[0];
    const float* qU = (const float*)d_in[1];
    const float* qV = (const float*)d_in[2];
    const float* kU = (const float*)d_in[3];
    const float* kV = (const float*)d_in[4];
    const float* vU = (const float*)d_in[5];
    const float* vV = (const float*)d_in[6];
    const float* cU = (const float*)d_in[7];
    const float* cV = (const float*)d_in[8];
    float* out = (float*)d_out;

    const int sm_g1  = 3 * 2 * 64 * PADH1 * 2;            // 30720
    const int sm_g2  = (2 * 128 * PADH2) * 2;             // 36864
    const int sm_att = (256 * PADA + 4 * 64 * PADA) * 2;  // 73728
    static int cfg_done = 0;
    if (!cfg_done) {
        cudaFuncSetAttribute(k_g1,
            cudaFuncAttributeMaxDynamicSharedMemorySize, sm_g1);
        cudaFuncSetAttribute(k_g2,
            cudaFuncAttributeMaxDynamicSharedMemorySize, sm_g2);
        cudaFuncSetAttribute(k_attn,
            cudaFuncAttributeMaxDynamicSharedMemorySize, sm_att);
        cfg_done = 1;
    }

    const dim3 thr(256);
    const dim3 g_g1a(NT / 64, 3);              // 128 x 3
    const dim3 g_g1b(NT / 64, 1);              // 128 x 1
    const dim3 g_qkv(C_ / 128, NT / 128, 3);   // 8 x 64 x 3
    const dim3 g_c(C_ / 128, NT / 128, 1);
    const dim3 g_att(T_ / 256, B_ * H_);       // 8 x 64

    __half* pXh; cudaGetSymbolAddress((void**)&pXh, g_xh);
    __half* pYh; cudaGetSymbolAddress((void**)&pYh, g_Yh);
    __half* pP;  cudaGetSymbolAddress((void**)&pP,  g_P);
    __half* pP2; cudaGetSymbolAddress((void**)&pP2, g_P2);
    __half* pWu; cudaGetSymbolAddress((void**)&pWu, g_Wu);

    k_cvt<<<2048, thr>>>(x);                                     // 1
    k_prepW<<<256, thr>>>(qV, kV, vV, cV);                       // 2
    k_prepU<<<256, thr>>>(qU, kU, vU, cU);                       // 3
    k_g1<<<g_g1a, thr, sm_g1>>>(pXh, 0, 192, pP);                // 4
    k_g2<<<g_qkv, thr, sm_g2>>>(pP, 192, pWu, 0, nullptr);       // 5
    k_attn<<<g_att, thr, sm_att>>>();                            // 6  (ncu -s 5)
    k_g1<<<g_g1b, thr, sm_g1>>>(pYh, 192, 64, pP2);              // 7
    k_g2<<<g_c, thr, sm_g2>>>(pP2, 64, pWu + 3 * 65536, 1, out); // 8
}

// round 8
// speedup vs baseline: 1.0659x; 1.0659x over previous
#include <cuda_runtime.h>
#include <cuda_fp16.h>
#include <cstdint>
#include <math.h>

#define B_ 4
#define T_ 2048
#define C_ 1024
#define H_ 16
#define D_ 64
#define R_ 64
#define NT 8192   // B*T

// ---------------- scratch (device globals; no allocation) ----------------
__device__ __half g_xh[NT * C_];      // x converted to half
__device__ __half g_W[256 * 1024];    // stacked scaled V-weights (half)
__device__ __half g_Wu[4 * 1024 * 64];// U weights (half)
__device__ __half g_P[NT * 192];      // rank-space P for q,k,v
__device__ __half g_P2[NT * 64];      // rank-space P for c-proj
__device__ __half g_Qh[NT * C_];      // [B,H,T,D], pre-scaled by 0.125*log2e
__device__ __half g_Kh[NT * C_];
__device__ __half g_Vh[NT * C_];
__device__ __half g_Yh[NT * C_];      // attention out [B,T,C]

// =================== portable tensor-core helpers (sm_80+) =================
__device__ __forceinline__ void mma_f16(float* d, const uint32_t* a,
                                        uint32_t b0, uint32_t b1) {
    asm volatile(
        "mma.sync.aligned.m16n8k16.row.col.f32.f16.f16.f32 "
        "{%0,%1,%2,%3}, {%4,%5,%6,%7}, {%8,%9}, {%0,%1,%2,%3};"
        : "+f"(d[0]), "+f"(d[1]), "+f"(d[2]), "+f"(d[3])
        : "r"(a[0]), "r"(a[1]), "r"(a[2]), "r"(a[3]), "r"(b0), "r"(b1));
}
__device__ __forceinline__ uint32_t smem_u32(const void* p) {
    uint32_t a;
    asm("{ .reg .u64 t; cvta.to.shared.u64 t, %1; cvt.u32.u64 %0, t; }"
        : "=r"(a) : "l"(p));
    return a;
}
__device__ __forceinline__ void cp16(uint32_t dst, const void* src) {
    asm volatile("cp.async.cg.shared.global [%0], [%1], 16;"
                 :: "r"(dst), "l"(src));
}
#define CP_COMMIT() asm volatile("cp.async.commit_group;" ::: "memory")
#define CP_WAIT(n)  asm volatile("cp.async.wait_group %0;" :: "n"(n) : "memory")
#define LDSM4(r, a)                                                         \
    asm volatile("ldmatrix.sync.aligned.m8n8.x4.shared.b16 "                \
                 "{%0,%1,%2,%3}, [%4];"                                     \
                 : "=r"((r)[0]), "=r"((r)[1]), "=r"((r)[2]), "=r"((r)[3])   \
                 : "r"(a))
#define LDSM4T(r, a)                                                        \
    asm volatile("ldmatrix.sync.aligned.m8n8.x4.trans.shared.b16 "          \
                 "{%0,%1,%2,%3}, [%4];"                                     \
                 : "=r"((r)[0]), "=r"((r)[1]), "=r"((r)[2]), "=r"((r)[3])   \
                 : "r"(a))
__device__ __forceinline__ uint32_t pack_h2(float lo, float hi) {
    __half2 h = __floats2half2_rn(lo, hi);
    return *(uint32_t*)&h;
}
__device__ __forceinline__ uint32_t h2exp2(uint32_t u) {
    uint32_t r;
    asm("ex2.approx.f16x2 %0, %1;" : "=r"(r) : "r"(u));
    return r;
}

// ---------------------------------------------------------------------------
// K_cvt: x fp32 -> half
// ---------------------------------------------------------------------------
__global__ __launch_bounds__(256) void k_cvt(const float* __restrict__ x) {
    const int base = (blockIdx.x * 256 + threadIdx.x) * 16;
    #pragma unroll
    for (int g = 0; g < 4; g++) {
        float4 v = *(const float4*)(x + base + g * 4);
        *(__half2*)(g_xh + base + g * 4)     = __floats2half2_rn(v.x, v.y);
        *(__half2*)(g_xh + base + g * 4 + 2) = __floats2half2_rn(v.z, v.w);
    }
}

// ---------------------------------------------------------------------------
// K_prepW: rows [0,64) Vq*s*0.125*log2e, [64,128) Vk*s, [128,192) Vv*s,
//          [192,256) Vc*s.
// ---------------------------------------------------------------------------
__global__ __launch_bounds__(256) void k_prepW(
    const float* __restrict__ qV, const float* __restrict__ kV,
    const float* __restrict__ vV, const float* __restrict__ cV) {
    const int b = blockIdx.x, tid = threadIdx.x;
    const int grp = b >> 6, r = b & 63;
    const float* Vsrc = (grp == 0) ? qV : (grp == 1) ? kV
                      : (grp == 2) ? vV : cV;
    float sc = powf((float)(r + 1), -0.7f);
    if (grp == 0) sc *= 0.125f * 1.4426950408889634f;
    const int c = tid * 4;
    float4 v = *(const float4*)(Vsrc + (size_t)r * 1024 + c);
    *(__half2*)(g_W + (size_t)b * 1024 + c)     = __floats2half2_rn(v.x * sc, v.y * sc);
    *(__half2*)(g_W + (size_t)b * 1024 + c + 2) = __floats2half2_rn(v.z * sc, v.w * sc);
}

__global__ __launch_bounds__(256) void k_prepU(
    const float* __restrict__ qU, const float* __restrict__ kU,
    const float* __restrict__ vU, const float* __restrict__ cU) {
    const float* Us[4] = {qU, kU, vU, cU};
    const int base = blockIdx.x * 1024 + threadIdx.x * 4;
    const int w = base >> 16, off = base & 65535;
    float4 u = *(const float4*)(Us[w] + off);
    *(__half2*)(g_Wu + base)     = __floats2half2_rn(u.x, u.y);
    *(__half2*)(g_Wu + base + 2) = __floats2half2_rn(u.z, u.w);
}

// ---------------------------------------------------------------------------
// K1: stage-1 GEMM  P[m, n] = A[m,:1024] @ W[wrow0+n, :1024]^T
// CTA tile 64 x NOUT. 8 warps (2m x 4n): warp tile 32 x NOUT/4
// -> 2mf x NOUT/32 nb independent mma chains (12 for NOUT=192).
// 3-stage cp.async pipeline over K-chunks of 32.
// ---------------------------------------------------------------------------
#define PADH1 40   // halfs; 80B row stride
template <int NOUT>
__global__ __launch_bounds__(256) void k_g1(const __half* __restrict__ A,
                                            int wrow0,
                                            __half* __restrict__ Pout) {
    extern __shared__ __half sg1h[];
    const int tid = threadIdx.x, w = tid >> 5, lane = tid & 31;
    const int quad = lane >> 2, qc = lane & 3;
    const int wm = w & 1, wn = w >> 1;          // 2m x 4n warps
    const int m0 = blockIdx.x * 64;
    constexpr int NB = NOUT / 32;               // chains per mf
    constexpr int STRIDE = (64 + NOUT) * PADH1; // halfs per stage
    const __half* Wp = g_W + (size_t)wrow0 * 1024;

    auto stage = [&](int ch, int s) {
        const int k0 = ch * 32;
        __half* base = sg1h + s * STRIDE;
        #pragma unroll
        for (int i = tid; i < (64 + NOUT) * 4; i += 256) {
            int row = i >> 2, c8 = (i & 3) * 8;
            const __half* src = (row < 64)
                ? A  + (size_t)(m0 + row) * 1024 + k0 + c8
                : Wp + (size_t)(row - 64) * 1024 + k0 + c8;
            cp16(smem_u32(base + row * PADH1 + c8), src);
        }
    };

    float acc[2][NB][4];
    #pragma unroll
    for (int mf = 0; mf < 2; mf++)
        #pragma unroll
        for (int nb = 0; nb < NB; nb++)
            #pragma unroll
            for (int i = 0; i < 4; i++) acc[mf][nb][i] = 0.f;

    stage(0, 0); CP_COMMIT();
    stage(1, 1); CP_COMMIT();

    for (int ch = 0; ch < 32; ch++) {
        if (ch + 2 < 32) stage(ch + 2, (ch + 2) % 3);
        CP_COMMIT();
        CP_WAIT(2);
        __syncthreads();
        const __half* Ab = sg1h + (ch % 3) * STRIDE;
        const __half* Bb = Ab + 64 * PADH1;
        #pragma unroll
        for (int kb = 0; kb < 2; kb++) {
            uint32_t a[2][4];
            #pragma unroll
            for (int mf = 0; mf < 2; mf++) {
                const __half* ap = Ab + (wm * 32 + mf * 16 + quad) * PADH1
                                 + kb * 16 + 2 * qc;
                a[mf][0] = *(const uint32_t*)(ap);
                a[mf][1] = *(const uint32_t*)(ap + 8 * PADH1);
                a[mf][2] = *(const uint32_t*)(ap + 8);
                a[mf][3] = *(const uint32_t*)(ap + 8 * PADH1 + 8);
            }
            #pragma unroll
            for (int nb = 0; nb < NB; nb++) {
                const __half* bp = Bb + (wn * (NOUT / 4) + nb * 8 + quad) * PADH1
                                 + kb * 16 + 2 * qc;
                uint32_t b0 = *(const uint32_t*)(bp);
                uint32_t b1 = *(const uint32_t*)(bp + 8);
                mma_f16(acc[0][nb], a[0], b0, b1);
                mma_f16(acc[1][nb], a[1], b0, b1);
            }
        }
        __syncthreads();
    }

    #pragma unroll
    for (int mf = 0; mf < 2; mf++) {
        const int row = m0 + wm * 32 + mf * 16 + quad;
        #pragma unroll
        for (int nb = 0; nb < NB; nb++) {
            const int col = wn * (NOUT / 4) + nb * 8 + 2 * qc;
            *(__half2*)(Pout + (size_t)row * NOUT + col) =
                __floats2half2_rn(acc[mf][nb][0], acc[mf][nb][1]);
            *(__half2*)(Pout + (size_t)(row + 8) * NOUT + col) =
                __floats2half2_rn(acc[mf][nb][2], acc[mf][nb][3]);
        }
    }
}

// ---------------------------------------------------------------------------
// K2: stage-2 GEMM  y[m,n] = P[m,:64] @ U[n,:64]^T, persistent N-strip.
// Each CTA: 128 rows, loops all 8 N-tiles of 128 cols; P A-tile + a-frags
// loaded once; U tiles double-buffered via cp.async.
// mode 0: blockIdx.y=z in {0,1,2} -> g_Q/K/V head-split.  mode 1: fp32 out.
// ---------------------------------------------------------------------------
#define PADH2 72   // halfs; 144B row stride
__global__ __launch_bounds__(256) void k_g2(const __half* __restrict__ Pbase,
                                            int ps,
                                            const __half* __restrict__ Wubase,
                                            int mode, float* __restrict__ outp) {
    extern __shared__ __half sg2h[];
    __half* As = sg2h;                 // [128][PADH2]
    __half* Ub = sg2h + 128 * PADH2;   // [2][128][PADH2]
    const int tid = threadIdx.x, w = tid >> 5, lane = tid & 31;
    const int quad = lane >> 2, qc = lane & 3;
    const int m0 = blockIdx.x * 128;
    const int z = blockIdx.y;
    const __half* Pin = Pbase + (mode == 0 ? z * 64 : 0);
    const __half* Wu  = Wubase + (mode == 0 ? z * 65536 : 0);

    // A tile (128 x 64) + U tile 0: one group; U tile 1: second group.
    #pragma unroll
    for (int t = 0; t < 4; t++) {
        int idx = tid + t * 256;
        int r = idx >> 3, c8 = (idx & 7) * 8;
        cp16(smem_u32(As + r * PADH2 + c8), Pin + (size_t)(m0 + r) * ps + c8);
    }
    #pragma unroll
    for (int t = 0; t < 4; t++) {
        int idx = tid + t * 256;
        int n = idx >> 3, c8 = (idx & 7) * 8;
        cp16(smem_u32(Ub + n * PADH2 + c8), Wu + (size_t)n * 64 + c8);
    }
    CP_COMMIT();
    #pragma unroll
    for (int t = 0; t < 4; t++) {
        int idx = tid + t * 256;
        int n = idx >> 3, c8 = (idx & 7) * 8;
        cp16(smem_u32(Ub + 128 * PADH2 + n * PADH2 + c8),
             Wu + (size_t)(128 + n) * 64 + c8);
    }
    CP_COMMIT();

    uint32_t a[4][4];
    const int row = m0 + w * 16 + quad;
    const int b = row >> 11, tt = row & (T_ - 1);

    for (int nt = 0; nt < 8; nt++) {
        CP_WAIT(1);
        if (nt == 7) CP_WAIT(0);
        __syncthreads();
        if (nt == 0) {         // a-frags once (As in first group)
            #pragma unroll
            for (int kb = 0; kb < 4; kb++) {
                const __half* ap = As + (w * 16 + quad) * PADH2
                                 + kb * 16 + 2 * qc;
                a[kb][0] = *(const uint32_t*)(ap);
                a[kb][1] = *(const uint32_t*)(ap + 8 * PADH2);
                a[kb][2] = *(const uint32_t*)(ap + 8);
                a[kb][3] = *(const uint32_t*)(ap + 8 * PADH2 + 8);
            }
        }
        const __half* Bs = Ub + (nt & 1) * 128 * PADH2;

        float acc[16][4];
        #pragma unroll
        for (int nb = 0; nb < 16; nb++)
            #pragma unroll
            for (int i = 0; i < 4; i++) acc[nb][i] = 0.f;

        #pragma unroll
        for (int kb = 0; kb < 4; kb++)
            #pragma unroll
            for (int nb = 0; nb < 16; nb++) {
                const __half* bp = Bs + (nb * 8 + quad) * PADH2
                                 + kb * 16 + 2 * qc;
                mma_f16(acc[nb], a[kb], *(const uint32_t*)(bp),
                        *(const uint32_t*)(bp + 8));
            }
        __syncthreads();       // done reading this U buffer
        if (nt + 2 < 8) {      // prefetch tile nt+2 into the freed buffer
            #pragma unroll
            for (int t = 0; t < 4; t++) {
                int idx = tid + t * 256;
                int n = idx >> 3, c8 = (idx & 7) * 8;
                cp16(smem_u32(Ub + (nt & 1) * 128 * PADH2 + n * PADH2 + c8),
                     Wu + (size_t)((nt + 2) * 128 + n) * 64 + c8);
            }
            CP_COMMIT();
        }

        const int n0 = nt * 128;
        if (mode == 0) {
            __half* dst = (z == 0) ? g_Qh : (z == 1) ? g_Kh : g_Vh;
            #pragma unroll
            for (int nb = 0; nb < 16; nb++) {
                const int col = n0 + nb * 8 + 2 * qc;
                const int h = col >> 6, d = col & 63;
                __half* p0 = dst + (((size_t)(b * H_ + h) * T_ + tt) * D_) + d;
                *(__half2*)p0 = __floats2half2_rn(acc[nb][0], acc[nb][1]);
                *(__half2*)(p0 + 8 * D_) = __floats2half2_rn(acc[nb][2], acc[nb][3]);
            }
        } else {
            #pragma unroll
            for (int nb = 0; nb < 16; nb++) {
                const int col = n0 + nb * 8 + 2 * qc;
                float* p0 = outp + (size_t)row * C_ + col;
                *(float2*)p0 = make_float2(acc[nb][0], acc[nb][1]);
                *(float2*)(p0 + 8 * C_) = make_float2(acc[nb][2], acc[nb][3]);
            }
        }
    }
}

// ---------------------------------------------------------------------------
// K3: causal flash attention, fp16 mma + ldmatrix.
// 256 q-rows/CTA, 8 warps x 32 rows, 64-key tiles, cp.async double buffer.
// exp via ex2.approx.f16x2 on packed logits; row-sums via a ones-column
// appended to V (col 64 = 1): Sum(p) accumulates in an extra mma chain.
// ---------------------------------------------------------------------------
#define PADA 72    // halfs; 144B stride
__global__ __launch_bounds__(256) void k_attn() {
    extern __shared__ __half sah[];
    __half* Qs  = sah;                      // [256][PADA]
    __half* Ksb = sah + 256 * PADA;         // [2][64][PADA]
    __half* Vsb = Ksb + 2 * 64 * PADA;      // [2][64][PADA] (+tail pad)
    const int tid = threadIdx.x, w = tid >> 5, lane = tid & 31;
    const int quad = lane >> 2, qc = lane & 3;
    const int msel = lane >> 3, rsel = lane & 7;
    const int mrow_a = (msel & 1) * 8 + rsel;   // Q / V(trans) row part
    const int mcol_a = (msel >> 1) * 8;
    const int mrow_b = (msel >> 1) * 8 + rsel;  // K row part
    const int mcol_b = (msel & 1) * 8;
    const int bh = blockIdx.y;
    const int qt = gridDim.x - 1 - blockIdx.x;  // heavy tiles first
    const int q0 = qt * 256;
    const __half* Qb = g_Qh + (size_t)bh * T_ * D_;
    const __half* Kb = g_Kh + (size_t)bh * T_ * D_;
    const __half* Vb = g_Vh + (size_t)bh * T_ * D_;
    const int nt = 4 * qt + 4;

    // ones-column for row-sum-by-MMA: V cols 64..71 = (1,0,...,0), both bufs
    for (int i = tid; i < 128; i += 256) {
        __half* row = Vsb + i * PADA + 64;
        row[0] = __float2half(1.0f);
        #pragma unroll
        for (int c = 1; c < 8; c++) row[c] = __float2half(0.0f);
    }

    auto stage = [&](int j, int buf) {
        const __half* Kt = Kb + (size_t)j * 64 * D_;
        const __half* Vt = Vb + (size_t)j * 64 * D_;
        __half* Kd = Ksb + buf * 64 * PADA;
        __half* Vd = Vsb + buf * 64 * PADA;
        #pragma unroll
        for (int t = 0; t < 2; t++) {
            int idx = tid + t * 256;
            int r = idx >> 3, c8 = (idx & 7) * 8;
            cp16(smem_u32(Kd + r * PADA + c8), Kt + (size_t)r * D_ + c8);
            cp16(smem_u32(Vd + r * PADA + c8), Vt + (size_t)r * D_ + c8);
        }
    };

    // Q tile (256 rows) + first K/V tile
    #pragma unroll
    for (int t = 0; t < 8; t++) {
        int idx = tid + t * 256;
        int r = idx >> 3, c8 = (idx & 7) * 8;
        cp16(smem_u32(Qs + r * PADA + c8), Qb + (size_t)(q0 + r) * D_ + c8);
    }
    stage(0, 0);
    CP_COMMIT();

    uint32_t qa[2][4][4];
    float o[2][8][4] = {};
    float oS[2][4] = {};    // ones-column accumulator: col 64 = Sum(p)
    int buf = 0;

    for (int j = 0; j < nt; j++) {
        if (j + 1 < nt) { stage(j + 1, buf ^ 1); CP_COMMIT(); CP_WAIT(1); }
        else            { CP_WAIT(0); }
        __syncthreads();
        const __half* Ks = Ksb + buf * 64 * PADA;
        const __half* Vs = Vsb + buf * 64 * PADA;

        if (j == 0) {        // Q a-frags once
            #pragma unroll
            for (int mf = 0; mf < 2; mf++)
                #pragma unroll
                for (int kb = 0; kb < 4; kb++)
                    LDSM4(qa[mf][kb],
                          smem_u32(Qs + (w * 32 + mf * 16 + mrow_a) * PADA
                                   + kb * 16 + mcol_a));
        }

        // ---- S = Q @ K^T : 32x64 per warp ----
        float s[2][8][4];
        #pragma unroll
        for (int mf = 0; mf < 2; mf++)
            #pragma unroll
            for (int nb = 0; nb < 8; nb++)
                #pragma unroll
                for (int i = 0; i < 4; i++) s[mf][nb][i] = 0.f;
        #pragma unroll
        for (int kb = 0; kb < 4; kb++)
            #pragma unroll
            for (int nbp = 0; nbp < 4; nbp++) {
                uint32_t bf[4];
                LDSM4(bf, smem_u32(Ks + (nbp * 16 + mrow_b) * PADA
                                   + kb * 16 + mcol_b));
                #pragma unroll
                for (int mf = 0; mf < 2; mf++) {
                    mma_f16(s[mf][2 * nbp],     qa[mf][kb], bf[0], bf[1]);
                    mma_f16(s[mf][2 * nbp + 1], qa[mf][kb], bf[2], bf[3]);
                }
            }

        // ---- causal mask on diagonal tiles (logits -> -inf) ----
        if (j >= nt - 4) {
            #pragma unroll
            for (int mf = 0; mf < 2; mf++) {
                const int rowrel0 = q0 + w * 32 + mf * 16 + quad - 64 * j;
                #pragma unroll
                for (int nb = 0; nb < 8; nb++) {
                    const int k0 = nb * 8 + 2 * qc;
                    if (k0 > rowrel0)         s[mf][nb][0] = -1e30f;
                    if (k0 + 1 > rowrel0)     s[mf][nb][1] = -1e30f;
                    if (k0 > rowrel0 + 8)     s[mf][nb][2] = -1e30f;
                    if (k0 + 1 > rowrel0 + 8) s[mf][nb][3] = -1e30f;
                }
            }
        }

        // ---- P = 2^S in f16x2; O += P @ [V | ones] ----
        #pragma unroll
        for (int kb = 0; kb < 4; kb++) {
            uint32_t pa[2][4];
            #pragma unroll
            for (int mf = 0; mf < 2; mf++) {
                pa[mf][0] = h2exp2(pack_h2(s[mf][2 * kb][0],     s[mf][2 * kb][1]));
                pa[mf][1] = h2exp2(pack_h2(s[mf][2 * kb][2],     s[mf][2 * kb][3]));
                pa[mf][2] = h2exp2(pack_h2(s[mf][2 * kb + 1][0], s[mf][2 * kb + 1][1]));
                pa[mf][3] = h2exp2(pack_h2(s[mf][2 * kb + 1][2], s[mf][2 * kb + 1][3]));
            }
            #pragma unroll
            for (int nbp = 0; nbp < 4; nbp++) {
                uint32_t vf[4];
                LDSM4T(vf, smem_u32(Vs + (kb * 16 + mrow_a) * PADA
                                    + nbp * 16 + mcol_a));
                #pragma unroll
                for (int mf = 0; mf < 2; mf++) {
                    mma_f16(o[mf][2 * nbp],     pa[mf], vf[0], vf[1]);
                    mma_f16(o[mf][2 * nbp + 1], pa[mf], vf[2], vf[3]);
                }
            }
            {   // ones column (cols 64..71; only first 8-col frag used)
                uint32_t vf[4];
                LDSM4T(vf, smem_u32(Vs + (kb * 16 + mrow_a) * PADA
                                    + 64 + mcol_a));
                mma_f16(oS[0], pa[0], vf[0], vf[1]);
                mma_f16(oS[1], pa[1], vf[0], vf[1]);
            }
        }
        __syncthreads();
        buf ^= 1;
    }

    // ---- epilogue: Sum(p) sits in col 64 (qc==0 lane of each quad) ----
    const int b = bh >> 4, h = bh & 15;
    #pragma unroll
    for (int mf = 0; mf < 2; mf++) {
        const float l0 = __shfl_sync(0xffffffffu, oS[mf][0], lane & 28);
        const float l1 = __shfl_sync(0xffffffffu, oS[mf][2], lane & 28);
        const float inv0 = 1.f / l0, inv1 = 1.f / l1;
        const int r0 = q0 + w * 32 + mf * 16 + quad;
        __half* y0 = g_Yh + ((size_t)b * T_ + r0) * C_ + h * 64;
        __half* y1 = y0 + 8 * C_;
        #pragma unroll
        for (int nb = 0; nb < 8; nb++) {
            const int c = nb * 8 + 2 * qc;
            *(__half2*)(y0 + c) = __floats2half2_rn(o[mf][nb][0] * inv0,
                                                    o[mf][nb][1] * inv0);
            *(__half2*)(y1 + c) = __floats2half2_rn(o[mf][nb][2] * inv1,
                                                    o[mf][nb][3] * inv1);
        }
    }
}

// ---------------------------------------------------------------------------
extern "C" void kernel_launch(void* const* d_in, const int* in_sizes, int n_in,
                              void* d_out, int out_size) {
    (void)in_sizes; (void)n_in; (void)out_size;
    const float* x  = (const float*)d_in[0];
    const float* qU = (const float*)d_in[1];
    const float* qV = (const float*)d_in[2];
    const float* kU = (const float*)d_in[3];
    const float* kV = (const float*)d_in[4];
    const float* vU = (const float*)d_in[5];
    const float* vV = (const float*)d_in[6];
    const float* cU = (const float*)d_in[7];
    const float* cV = (const float*)d_in[8];
    float* out = (float*)d_out;

    const int sm_g1a = 3 * (64 + 192) * PADH1 * 2;              // 61440
    const int sm_g1b = 3 * (64 + 64) * PADH1 * 2;               // 30720
    const int sm_g2  = 3 * 128 * PADH2 * 2;                     // 55296
    const int sm_att = (256 * PADA + 4 * 64 * PADA) * 2 + 512;  // 74240
    static int cfg_done = 0;
    if (!cfg_done) {
        cudaFuncSetAttribute(k_g1<192>,
            cudaFuncAttributeMaxDynamicSharedMemorySize, sm_g1a);
        cudaFuncSetAttribute(k_g1<64>,
            cudaFuncAttributeMaxDynamicSharedMemorySize, sm_g1b);
        cudaFuncSetAttribute(k_g2,
            cudaFuncAttributeMaxDynamicSharedMemorySize, sm_g2);
        cudaFuncSetAttribute(k_attn,
            cudaFuncAttributeMaxDynamicSharedMemorySize, sm_att);
        cfg_done = 1;
    }

    const dim3 thr(256);
    const dim3 g_g1(NT / 64);                  // 128
    const dim3 g_qkv(NT / 128, 3);             // 64 x 3
    const dim3 g_c(NT / 128, 1);               // 64
    const dim3 g_att(T_ / 256, B_ * H_);       // 8 x 64

    __half* pXh; cudaGetSymbolAddress((void**)&pXh, g_xh);
    __half* pYh; cudaGetSymbolAddress((void**)&pYh, g_Yh);
    __half* pP;  cudaGetSymbolAddress((void**)&pP,  g_P);
    __half* pP2; cudaGetSymbolAddress((void**)&pP2, g_P2);
    __half* pWu; cudaGetSymbolAddress((void**)&pWu, g_Wu);

    k_cvt<<<2048, thr>>>(x);                                     // 1
    k_prepW<<<256, thr>>>(qV, kV, vV, cV);                       // 2
    k_prepU<<<256, thr>>>(qU, kU, vU, cU);                       // 3
    k_g1<192><<<g_g1, thr, sm_g1a>>>(pXh, 0, pP);                // 4
    k_g2<<<g_qkv, thr, sm_g2>>>(pP, 192, pWu, 0, nullptr);       // 5
    k_attn<<<g_att, thr, sm_att>>>();                            // 6
    k_g1<64><<<g_g1, thr, sm_g1b>>>(pYh, 192, pP2);              // 7
    k_g2<<<g_c, thr, sm_g2>>>(pP2, 64, pWu + 3 * 65536, 1, out); // 8
}

// round 9
// speedup vs baseline: 1.0866x; 1.0194x over previous
#include <cuda_runtime.h>
#include <cuda_fp16.h>
#include <cstdint>
#include <math.h>

#define B_ 4
#define T_ 2048
#define C_ 1024
#define H_ 16
#define D_ 64
#define R_ 64
#define NT 8192   // B*T

// ---------------- scratch (device globals; no allocation) ----------------
__device__ __half g_xh[NT * C_];      // x converted to half
__device__ __half g_W[256 * 1024];    // stacked scaled V-weights (half)
__device__ __half g_Wu[4 * 1024 * 64];// U weights (half)
__device__ __half g_P[NT * 192];      // rank-space P for q,k,v
__device__ __half g_P2[NT * 64];      // rank-space P for c-proj
__device__ __half g_Qh[NT * C_];      // [B,H,T,D], pre-scaled by 0.125*log2e
__device__ __half g_Kh[NT * C_];
__device__ __half g_Vh[NT * C_];
__device__ __half g_Yh[NT * C_];      // attention out [B,T,C]

// =================== portable tensor-core helpers (sm_80+) =================
__device__ __forceinline__ void mma_f16(float* d, const uint32_t* a,
                                        uint32_t b0, uint32_t b1) {
    asm volatile(
        "mma.sync.aligned.m16n8k16.row.col.f32.f16.f16.f32 "
        "{%0,%1,%2,%3}, {%4,%5,%6,%7}, {%8,%9}, {%0,%1,%2,%3};"
        : "+f"(d[0]), "+f"(d[1]), "+f"(d[2]), "+f"(d[3])
        : "r"(a[0]), "r"(a[1]), "r"(a[2]), "r"(a[3]), "r"(b0), "r"(b1));
}
__device__ __forceinline__ uint32_t smem_u32(const void* p) {
    uint32_t a;
    asm("{ .reg .u64 t; cvta.to.shared.u64 t, %1; cvt.u32.u64 %0, t; }"
        : "=r"(a) : "l"(p));
    return a;
}
__device__ __forceinline__ void cp16(uint32_t dst, const void* src) {
    asm volatile("cp.async.cg.shared.global [%0], [%1], 16;"
                 :: "r"(dst), "l"(src));
}
#define CP_COMMIT() asm volatile("cp.async.commit_group;" ::: "memory")
#define CP_WAIT(n)  asm volatile("cp.async.wait_group %0;" :: "n"(n) : "memory")
#define LDSM4(r, a)                                                         \
    asm volatile("ldmatrix.sync.aligned.m8n8.x4.shared.b16 "                \
                 "{%0,%1,%2,%3}, [%4];"                                     \
                 : "=r"((r)[0]), "=r"((r)[1]), "=r"((r)[2]), "=r"((r)[3])   \
                 : "r"(a))
#define LDSM4T(r, a)                                                        \
    asm volatile("ldmatrix.sync.aligned.m8n8.x4.trans.shared.b16 "          \
                 "{%0,%1,%2,%3}, [%4];"                                     \
                 : "=r"((r)[0]), "=r"((r)[1]), "=r"((r)[2]), "=r"((r)[3])   \
                 : "r"(a))
__device__ __forceinline__ uint32_t pack_h2(float lo, float hi) {
    __half2 h = __floats2half2_rn(lo, hi);
    return *(uint32_t*)&h;
}
__device__ __forceinline__ uint32_t h2exp2(uint32_t u) {
    uint32_t r;
    asm("ex2.approx.f16x2 %0, %1;" : "=r"(r) : "r"(u));
    return r;
}

// ---------------------------------------------------------------------------
// K_cvt: x fp32 -> half
// ---------------------------------------------------------------------------
__global__ __launch_bounds__(256) void k_cvt(const float* __restrict__ x) {
    const int base = (blockIdx.x * 256 + threadIdx.x) * 16;
    #pragma unroll
    for (int g = 0; g < 4; g++) {
        float4 v = *(const float4*)(x + base + g * 4);
        *(__half2*)(g_xh + base + g * 4)     = __floats2half2_rn(v.x, v.y);
        *(__half2*)(g_xh + base + g * 4 + 2) = __floats2half2_rn(v.z, v.w);
    }
}

// ---------------------------------------------------------------------------
// K_prep: blocks [0,256): scaled V-weights -> g_W
//         blocks [256,512): U weights -> g_Wu
// ---------------------------------------------------------------------------
__global__ __launch_bounds__(256) void k_prep(
    const float* __restrict__ qU, const float* __restrict__ kU,
    const float* __restrict__ vU, const float* __restrict__ cU,
    const float* __restrict__ qV, const float* __restrict__ kV,
    const float* __restrict__ vV, const float* __restrict__ cV) {
    const int b = blockIdx.x, tid = threadIdx.x;
    if (b < 256) {
        const int grp = b >> 6, r = b & 63;
        const float* Vsrc = (grp == 0) ? qV : (grp == 1) ? kV
                          : (grp == 2) ? vV : cV;
        float sc = powf((float)(r + 1), -0.7f);
        if (grp == 0) sc *= 0.125f * 1.4426950408889634f;
        const int c = tid * 4;
        float4 v = *(const float4*)(Vsrc + (size_t)r * 1024 + c);
        *(__half2*)(g_W + (size_t)b * 1024 + c)     = __floats2half2_rn(v.x * sc, v.y * sc);
        *(__half2*)(g_W + (size_t)b * 1024 + c + 2) = __floats2half2_rn(v.z * sc, v.w * sc);
    } else {
        const float* Us[4] = {qU, kU, vU, cU};
        const int base = (b - 256) * 1024 + tid * 4;
        const int w = base >> 16, off = base & 65535;
        float4 u = *(const float4*)(Us[w] + off);
        *(__half2*)(g_Wu + base)     = __floats2half2_rn(u.x, u.y);
        *(__half2*)(g_Wu + base + 2) = __floats2half2_rn(u.z, u.w);
    }
}

// ---------------------------------------------------------------------------
// K1a: stage-1 qkv GEMM  P[m, n] = x[m,:1024] @ W[n,:1024]^T, NOUT=192.
// 128 threads/CTA, tile 32x192, grid 256 -> ~2 independent CTAs per SM.
// Warp: 32 rows x 48 cols = 12 chains. 3-stage cp.async pipeline, chunks 32.
// ---------------------------------------------------------------------------
#define PADH1 40   // halfs; 80B row stride
__global__ __launch_bounds__(128) void k_g1a(const __half* __restrict__ A,
                                             __half* __restrict__ Pout) {
    extern __shared__ __half sg1h[];
    const int tid = threadIdx.x, w = tid >> 5, lane = tid & 31;
    const int quad = lane >> 2, qc = lane & 3;
    const int m0 = blockIdx.x * 32;
    constexpr int STRIDE = (32 + 192) * PADH1;   // halfs per stage

    auto stage = [&](int ch, int s) {
        const int k0 = ch * 32;
        __half* base = sg1h + s * STRIDE;
        #pragma unroll
        for (int i = tid; i < (32 + 192) * 4; i += 128) {
            int row = i >> 2, c8 = (i & 3) * 8;
            const __half* src = (row < 32)
                ? A   + (size_t)(m0 + row) * 1024 + k0 + c8
                : g_W + (size_t)(row - 32) * 1024 + k0 + c8;
            cp16(smem_u32(base + row * PADH1 + c8), src);
        }
    };

    float acc[2][6][4];
    #pragma unroll
    for (int mf = 0; mf < 2; mf++)
        #pragma unroll
        for (int nb = 0; nb < 6; nb++)
            #pragma unroll
            for (int i = 0; i < 4; i++) acc[mf][nb][i] = 0.f;

    stage(0, 0); CP_COMMIT();
    stage(1, 1); CP_COMMIT();

    for (int ch = 0; ch < 32; ch++) {
        if (ch + 2 < 32) stage(ch + 2, (ch + 2) % 3);
        CP_COMMIT();
        CP_WAIT(2);
        __syncthreads();
        const __half* Ab = sg1h + (ch % 3) * STRIDE;
        const __half* Bb = Ab + 32 * PADH1;
        #pragma unroll
        for (int kb = 0; kb < 2; kb++) {
            uint32_t a[2][4];
            #pragma unroll
            for (int mf = 0; mf < 2; mf++) {
                const __half* ap = Ab + (mf * 16 + quad) * PADH1
                                 + kb * 16 + 2 * qc;
                a[mf][0] = *(const uint32_t*)(ap);
                a[mf][1] = *(const uint32_t*)(ap + 8 * PADH1);
                a[mf][2] = *(const uint32_t*)(ap + 8);
                a[mf][3] = *(const uint32_t*)(ap + 8 * PADH1 + 8);
            }
            #pragma unroll
            for (int nb = 0; nb < 6; nb++) {
                const __half* bp = Bb + (w * 48 + nb * 8 + quad) * PADH1
                                 + kb * 16 + 2 * qc;
                uint32_t b0 = *(const uint32_t*)(bp);
                uint32_t b1 = *(const uint32_t*)(bp + 8);
                mma_f16(acc[0][nb], a[0], b0, b1);
                mma_f16(acc[1][nb], a[1], b0, b1);
            }
        }
        __syncthreads();
    }

    #pragma unroll
    for (int mf = 0; mf < 2; mf++) {
        const int row = m0 + mf * 16 + quad;
        #pragma unroll
        for (int nb = 0; nb < 6; nb++) {
            const int col = w * 48 + nb * 8 + 2 * qc;
            *(__half2*)(Pout + (size_t)row * 192 + col) =
                __floats2half2_rn(acc[mf][nb][0], acc[mf][nb][1]);
            *(__half2*)(Pout + (size_t)(row + 8) * 192 + col) =
                __floats2half2_rn(acc[mf][nb][2], acc[mf][nb][3]);
        }
    }
}

// ---------------------------------------------------------------------------
// K1b: stage-1 c-proj GEMM  P2[m, n] = Y[m,:1024] @ W[192+n,:1024]^T, NOUT=64
// 256 threads, tile 64x64 (as R8).
// ---------------------------------------------------------------------------
__global__ __launch_bounds__(256) void k_g1b(__half* __restrict__ Pout) {
    extern __shared__ __half sg1bh[];
    const int tid = threadIdx.x, w = tid >> 5, lane = tid & 31;
    const int quad = lane >> 2, qc = lane & 3;
    const int wm = w & 1, wn = w >> 1;
    const int m0 = blockIdx.x * 64;
    constexpr int STRIDE = 128 * PADH1;
    const __half* Wp = g_W + (size_t)192 * 1024;

    auto stage = [&](int ch, int s) {
        const int k0 = ch * 32;
        __half* base = sg1bh + s * STRIDE;
        #pragma unroll
        for (int i = tid; i < 128 * 4; i += 256) {
            int row = i >> 2, c8 = (i & 3) * 8;
            const __half* src = (row < 64)
                ? g_Yh + (size_t)(m0 + row) * 1024 + k0 + c8
                : Wp   + (size_t)(row - 64) * 1024 + k0 + c8;
            cp16(smem_u32(base + row * PADH1 + c8), src);
        }
    };

    float acc[2][2][4] = {};
    stage(0, 0); CP_COMMIT();
    stage(1, 1); CP_COMMIT();

    for (int ch = 0; ch < 32; ch++) {
        if (ch + 2 < 32) stage(ch + 2, (ch + 2) % 3);
        CP_COMMIT();
        CP_WAIT(2);
        __syncthreads();
        const __half* Ab = sg1bh + (ch % 3) * STRIDE;
        const __half* Bb = Ab + 64 * PADH1;
        #pragma unroll
        for (int kb = 0; kb < 2; kb++) {
            uint32_t a[2][4];
            #pragma unroll
            for (int mf = 0; mf < 2; mf++) {
                const __half* ap = Ab + (wm * 32 + mf * 16 + quad) * PADH1
                                 + kb * 16 + 2 * qc;
                a[mf][0] = *(const uint32_t*)(ap);
                a[mf][1] = *(const uint32_t*)(ap + 8 * PADH1);
                a[mf][2] = *(const uint32_t*)(ap + 8);
                a[mf][3] = *(const uint32_t*)(ap + 8 * PADH1 + 8);
            }
            #pragma unroll
            for (int nb = 0; nb < 2; nb++) {
                const __half* bp = Bb + (wn * 16 + nb * 8 + quad) * PADH1
                                 + kb * 16 + 2 * qc;
                uint32_t b0 = *(const uint32_t*)(bp);
                uint32_t b1 = *(const uint32_t*)(bp + 8);
                mma_f16(acc[0][nb], a[0], b0, b1);
                mma_f16(acc[1][nb], a[1], b0, b1);
            }
        }
        __syncthreads();
    }

    #pragma unroll
    for (int mf = 0; mf < 2; mf++) {
        const int row = m0 + wm * 32 + mf * 16 + quad;
        #pragma unroll
        for (int nb = 0; nb < 2; nb++) {
            const int col = wn * 16 + nb * 8 + 2 * qc;
            *(__half2*)(Pout + (size_t)row * 64 + col) =
                __floats2half2_rn(acc[mf][nb][0], acc[mf][nb][1]);
            *(__half2*)(Pout + (size_t)(row + 8) * 64 + col) =
                __floats2half2_rn(acc[mf][nb][2], acc[mf][nb][3]);
        }
    }
}

// ---------------------------------------------------------------------------
// K2: stage-2 GEMM  y[m,n] = P[m,:64] @ U[n,:64]^T, persistent N-strip.
// ---------------------------------------------------------------------------
#define PADH2 72   // halfs; 144B row stride
__global__ __launch_bounds__(256) void k_g2(const __half* __restrict__ Pbase,
                                            int ps,
                                            const __half* __restrict__ Wubase,
                                            int mode, float* __restrict__ outp) {
    extern __shared__ __half sg2h[];
    __half* As = sg2h;                 // [128][PADH2]
    __half* Ub = sg2h + 128 * PADH2;   // [2][128][PADH2]
    const int tid = threadIdx.x, w = tid >> 5, lane = tid & 31;
    const int quad = lane >> 2, qc = lane & 3;
    const int m0 = blockIdx.x * 128;
    const int z = blockIdx.y;
    const __half* Pin = Pbase + (mode == 0 ? z * 64 : 0);
    const __half* Wu  = Wubase + (mode == 0 ? z * 65536 : 0);

    #pragma unroll
    for (int t = 0; t < 4; t++) {
        int idx = tid + t * 256;
        int r = idx >> 3, c8 = (idx & 7) * 8;
        cp16(smem_u32(As + r * PADH2 + c8), Pin + (size_t)(m0 + r) * ps + c8);
    }
    #pragma unroll
    for (int t = 0; t < 4; t++) {
        int idx = tid + t * 256;
        int n = idx >> 3, c8 = (idx & 7) * 8;
        cp16(smem_u32(Ub + n * PADH2 + c8), Wu + (size_t)n * 64 + c8);
    }
    CP_COMMIT();
    #pragma unroll
    for (int t = 0; t < 4; t++) {
        int idx = tid + t * 256;
        int n = idx >> 3, c8 = (idx & 7) * 8;
        cp16(smem_u32(Ub + 128 * PADH2 + n * PADH2 + c8),
             Wu + (size_t)(128 + n) * 64 + c8);
    }
    CP_COMMIT();

    uint32_t a[4][4];
    const int row = m0 + w * 16 + quad;
    const int b = row >> 11, tt = row & (T_ - 1);

    for (int nt = 0; nt < 8; nt++) {
        CP_WAIT(1);
        if (nt == 7) CP_WAIT(0);
        __syncthreads();
        if (nt == 0) {
            #pragma unroll
            for (int kb = 0; kb < 4; kb++) {
                const __half* ap = As + (w * 16 + quad) * PADH2
                                 + kb * 16 + 2 * qc;
                a[kb][0] = *(const uint32_t*)(ap);
                a[kb][1] = *(const uint32_t*)(ap + 8 * PADH2);
                a[kb][2] = *(const uint32_t*)(ap + 8);
                a[kb][3] = *(const uint32_t*)(ap + 8 * PADH2 + 8);
            }
        }
        const __half* Bs = Ub + (nt & 1) * 128 * PADH2;

        float acc[16][4];
        #pragma unroll
        for (int nb = 0; nb < 16; nb++)
            #pragma unroll
            for (int i = 0; i < 4; i++) acc[nb][i] = 0.f;

        #pragma unroll
        for (int kb = 0; kb < 4; kb++)
            #pragma unroll
            for (int nb = 0; nb < 16; nb++) {
                const __half* bp = Bs + (nb * 8 + quad) * PADH2
                                 + kb * 16 + 2 * qc;
                mma_f16(acc[nb], a[kb], *(const uint32_t*)(bp),
                        *(const uint32_t*)(bp + 8));
            }
        __syncthreads();
        if (nt + 2 < 8) {
            #pragma unroll
            for (int t = 0; t < 4; t++) {
                int idx = tid + t * 256;
                int n = idx >> 3, c8 = (idx & 7) * 8;
                cp16(smem_u32(Ub + (nt & 1) * 128 * PADH2 + n * PADH2 + c8),
                     Wu + (size_t)((nt + 2) * 128 + n) * 64 + c8);
            }
            CP_COMMIT();
        }

        const int n0 = nt * 128;
        if (mode == 0) {
            __half* dst = (z == 0) ? g_Qh : (z == 1) ? g_Kh : g_Vh;
            #pragma unroll
            for (int nb = 0; nb < 16; nb++) {
                const int col = n0 + nb * 8 + 2 * qc;
                const int h = col >> 6, d = col & 63;
                __half* p0 = dst + (((size_t)(b * H_ + h) * T_ + tt) * D_) + d;
                *(__half2*)p0 = __floats2half2_rn(acc[nb][0], acc[nb][1]);
                *(__half2*)(p0 + 8 * D_) = __floats2half2_rn(acc[nb][2], acc[nb][3]);
            }
        } else {
            #pragma unroll
            for (int nb = 0; nb < 16; nb++) {
                const int col = n0 + nb * 8 + 2 * qc;
                float* p0 = outp + (size_t)row * C_ + col;
                *(float2*)p0 = make_float2(acc[nb][0], acc[nb][1]);
                *(float2*)(p0 + 8 * C_) = make_float2(acc[nb][2], acc[nb][3]);
            }
        }
    }
}

// ---------------------------------------------------------------------------
// K3: causal flash attention, fp16 mma + ldmatrix.
// 128 q-rows/CTA, 8 warps x 16 rows, 64-key tiles, cp.async double buffer.
// __launch_bounds__(256,2): <=128 regs -> 2 CTAs/SM -> 4 warps/SMSP.
// exp via ex2.approx.f16x2; row-sums via ones-column in V (col 64).
// ---------------------------------------------------------------------------
#define PADA 72    // halfs; 144B stride
__global__ __launch_bounds__(256, 2) void k_attn() {
    extern __shared__ __half sah[];
    __half* Qs  = sah;                      // [128][PADA]
    __half* Ksb = sah + 128 * PADA;         // [2][64][PADA]
    __half* Vsb = Ksb + 2 * 64 * PADA;      // [2][64][PADA] (+tail pad)
    const int tid = threadIdx.x, w = tid >> 5, lane = tid & 31;
    const int quad = lane >> 2, qc = lane & 3;
    const int msel = lane >> 3, rsel = lane & 7;
    const int mrow_a = (msel & 1) * 8 + rsel;   // Q / V(trans) row part
    const int mcol_a = (msel >> 1) * 8;
    const int mrow_b = (msel >> 1) * 8 + rsel;  // K row part
    const int mcol_b = (msel & 1) * 8;
    const int bh = blockIdx.y;
    const int qt = gridDim.x - 1 - blockIdx.x;  // heavy tiles first
    const int q0 = qt * 128;
    const __half* Qb = g_Qh + (size_t)bh * T_ * D_;
    const __half* Kb = g_Kh + (size_t)bh * T_ * D_;
    const __half* Vb = g_Vh + (size_t)bh * T_ * D_;
    const int nt = 2 * qt + 2;

    // ones-column for row-sum-by-MMA: V cols 64..71 = (1,0,...,0), both bufs
    for (int i = tid; i < 128; i += 256) {
        __half* row = Vsb + i * PADA + 64;
        row[0] = __float2half(1.0f);
        #pragma unroll
        for (int c = 1; c < 8; c++) row[c] = __float2half(0.0f);
    }

    auto stage = [&](int j, int buf) {
        const __half* Kt = Kb + (size_t)j * 64 * D_;
        const __half* Vt = Vb + (size_t)j * 64 * D_;
        __half* Kd = Ksb + buf * 64 * PADA;
        __half* Vd = Vsb + buf * 64 * PADA;
        #pragma unroll
        for (int t = 0; t < 2; t++) {
            int idx = tid + t * 256;
            int r = idx >> 3, c8 = (idx & 7) * 8;
            cp16(smem_u32(Kd + r * PADA + c8), Kt + (size_t)r * D_ + c8);
            cp16(smem_u32(Vd + r * PADA + c8), Vt + (size_t)r * D_ + c8);
        }
    };

    // Q tile (128 rows) + first K/V tile
    #pragma unroll
    for (int t = 0; t < 4; t++) {
        int idx = tid + t * 256;
        int r = idx >> 3, c8 = (idx & 7) * 8;
        cp16(smem_u32(Qs + r * PADA + c8), Qb + (size_t)(q0 + r) * D_ + c8);
    }
    stage(0, 0);
    CP_COMMIT();

    uint32_t qa[4][4];
    float o[8][4] = {};
    float oS[4] = {};       // ones-column accumulator: col 64 = Sum(p)
    int buf = 0;

    for (int j = 0; j < nt; j++) {
        if (j + 1 < nt) { stage(j + 1, buf ^ 1); CP_COMMIT(); CP_WAIT(1); }
        else            { CP_WAIT(0); }
        __syncthreads();
        const __half* Ks = Ksb + buf * 64 * PADA;
        const __half* Vs = Vsb + buf * 64 * PADA;

        if (j == 0) {        // Q a-frags once
            #pragma unroll
            for (int kb = 0; kb < 4; kb++)
                LDSM4(qa[kb], smem_u32(Qs + (w * 16 + mrow_a) * PADA
                                       + kb * 16 + mcol_a));
        }

        // ---- S = Q @ K^T : 16x64 per warp ----
        float s[8][4];
        #pragma unroll
        for (int nb = 0; nb < 8; nb++)
            #pragma unroll
            for (int i = 0; i < 4; i++) s[nb][i] = 0.f;
        #pragma unroll
        for (int kb = 0; kb < 4; kb++)
            #pragma unroll
            for (int nbp = 0; nbp < 4; nbp++) {
                uint32_t bf[4];
                LDSM4(bf, smem_u32(Ks + (nbp * 16 + mrow_b) * PADA
                                   + kb * 16 + mcol_b));
                mma_f16(s[2 * nbp],     qa[kb], bf[0], bf[1]);
                mma_f16(s[2 * nbp + 1], qa[kb], bf[2], bf[3]);
            }

        // ---- causal mask on diagonal tiles ----
        if (j >= nt - 2) {
            const int rowrel0 = q0 + w * 16 + quad - 64 * j;
            #pragma unroll
            for (int nb = 0; nb < 8; nb++) {
                const int k0 = nb * 8 + 2 * qc;
                if (k0 > rowrel0)         s[nb][0] = -1e30f;
                if (k0 + 1 > rowrel0)     s[nb][1] = -1e30f;
                if (k0 > rowrel0 + 8)     s[nb][2] = -1e30f;
                if (k0 + 1 > rowrel0 + 8) s[nb][3] = -1e30f;
            }
        }

        // ---- P = 2^S in f16x2; O += P @ [V | ones] ----
        #pragma unroll
        for (int kb = 0; kb < 4; kb++) {
            uint32_t pa[4];
            pa[0] = h2exp2(pack_h2(s[2 * kb][0],     s[2 * kb][1]));
            pa[1] = h2exp2(pack_h2(s[2 * kb][2],     s[2 * kb][3]));
            pa[2] = h2exp2(pack_h2(s[2 * kb + 1][0], s[2 * kb + 1][1]));
            pa[3] = h2exp2(pack_h2(s[2 * kb + 1][2], s[2 * kb + 1][3]));
            #pragma unroll
            for (int nbp = 0; nbp < 4; nbp++) {
                uint32_t vf[4];
                LDSM4T(vf, smem_u32(Vs + (kb * 16 + mrow_a) * PADA
                                    + nbp * 16 + mcol_a));
                mma_f16(o[2 * nbp],     pa, vf[0], vf[1]);
                mma_f16(o[2 * nbp + 1], pa, vf[2], vf[3]);
            }
            {   // ones column (cols 64..71)
                uint32_t vf[4];
                LDSM4T(vf, smem_u32(Vs + (kb * 16 + mrow_a) * PADA
                                    + 64 + mcol_a));
                mma_f16(oS, pa, vf[0], vf[1]);
            }
        }
        __syncthreads();
        buf ^= 1;
    }

    // ---- epilogue: Sum(p) in col 64 (qc==0 lane of each quad) ----
    const int b = bh >> 4, h = bh & 15;
    const float l0 = __shfl_sync(0xffffffffu, oS[0], lane & 28);
    const float l1 = __shfl_sync(0xffffffffu, oS[2], lane & 28);
    const float inv0 = 1.f / l0, inv1 = 1.f / l1;
    const int r0 = q0 + w * 16 + quad;
    __half* y0 = g_Yh + ((size_t)b * T_ + r0) * C_ + h * 64;
    __half* y1 = y0 + 8 * C_;
    #pragma unroll
    for (int nb = 0; nb < 8; nb++) {
        const int c = nb * 8 + 2 * qc;
        *(__half2*)(y0 + c) = __floats2half2_rn(o[nb][0] * inv0,
                                                o[nb][1] * inv0);
        *(__half2*)(y1 + c) = __floats2half2_rn(o[nb][2] * inv1,
                                                o[nb][3] * inv1);
    }
}

// ---------------------------------------------------------------------------
extern "C" void kernel_launch(void* const* d_in, const int* in_sizes, int n_in,
                              void* d_out, int out_size) {
    (void)in_sizes; (void)n_in; (void)out_size;
    const float* x  = (const float*)d_in[0];
    const float* qU = (const float*)d_in[1];
    const float* qV = (const float*)d_in[2];
    const float* kU = (const float*)d_in[3];
    const float* kV = (const float*)d_in[4];
    const float* vU = (const float*)d_in[5];
    const float* vV = (const float*)d_in[6];
    const float* cU = (const float*)d_in[7];
    const float* cV = (const float*)d_in[8];
    float* out = (float*)d_out;

    const int sm_g1a = 3 * (32 + 192) * PADH1 * 2;              // 53760
    const int sm_g1b = 3 * 128 * PADH1 * 2;                     // 30720
    const int sm_g2  = 3 * 128 * PADH2 * 2;                     // 55296
    const int sm_att = (128 * PADA + 4 * 64 * PADA) * 2 + 512;  // 55808
    static int cfg_done = 0;
    if (!cfg_done) {
        cudaFuncSetAttribute(k_g1a,
            cudaFuncAttributeMaxDynamicSharedMemorySize, sm_g1a);
        cudaFuncSetAttribute(k_g1b,
            cudaFuncAttributeMaxDynamicSharedMemorySize, sm_g1b);
        cudaFuncSetAttribute(k_g2,
            cudaFuncAttributeMaxDynamicSharedMemorySize, sm_g2);
        cudaFuncSetAttribute(k_attn,
            cudaFuncAttributeMaxDynamicSharedMemorySize, sm_att);
        cfg_done = 1;
    }

    const dim3 g_qkv(NT / 128, 3);             // 64 x 3
    const dim3 g_c(NT / 128, 1);               // 64
    const dim3 g_att(T_ / 128, B_ * H_);       // 16 x 64

    __half* pXh; cudaGetSymbolAddress((void**)&pXh, g_xh);
    __half* pP;  cudaGetSymbolAddress((void**)&pP,  g_P);
    __half* pP2; cudaGetSymbolAddress((void**)&pP2, g_P2);
    __half* pWu; cudaGetSymbolAddress((void**)&pWu, g_Wu);

    k_cvt<<<2048, 256>>>(x);                                       // 1
    k_prep<<<512, 256>>>(qU, kU, vU, cU, qV, kV, vV, cV);          // 2
    k_g1a<<<NT / 32, 128, sm_g1a>>>(pXh, pP);                      // 3
    k_g2<<<g_qkv, 256, sm_g2>>>(pP, 192, pWu, 0, nullptr);         // 4
    k_attn<<<g_att, 256, sm_att>>>();                              // 5
    k_g1b<<<NT / 64, 256, sm_g1b>>>(pP2);                          // 6
    k_g2<<<g_c, 256, sm_g2>>>(pP2, 64, pWu + 3 * 65536, 1, out);   // 7
}

// round 10
// speedup vs baseline: 1.1405x; 1.0495x over previous
#include <cuda_runtime.h>
#include <cuda_fp16.h>
#include <cstdint>
#include <math.h>

#define B_ 4
#define T_ 2048
#define C_ 1024
#define H_ 16
#define D_ 64
#define R_ 64
#define NT 8192   // B*T

// ---------------- scratch (device globals; no allocation) ----------------
__device__ __half g_xh[NT * C_];      // x converted to half
__device__ __half g_W[256 * 1024];    // stacked scaled V-weights (half)
__device__ __half g_Wu[4 * 1024 * 64];// U weights (half)
__device__ __half g_P[NT * 192];      // rank-space P for q,k,v
__device__ __half g_P2[NT * 64];      // rank-space P for c-proj
__device__ __half g_Qh[NT * C_];      // [B,H,T,D], pre-scaled by 0.125*log2e
__device__ __half g_Kh[NT * C_];
__device__ __half g_Vh[NT * C_];
__device__ __half g_Yh[NT * C_];      // attention out [B,T,C]

// =================== portable tensor-core helpers (sm_80+) =================
__device__ __forceinline__ void mma_f16(float* d, const uint32_t* a,
                                        uint32_t b0, uint32_t b1) {
    asm volatile(
        "mma.sync.aligned.m16n8k16.row.col.f32.f16.f16.f32 "
        "{%0,%1,%2,%3}, {%4,%5,%6,%7}, {%8,%9}, {%0,%1,%2,%3};"
        : "+f"(d[0]), "+f"(d[1]), "+f"(d[2]), "+f"(d[3])
        : "r"(a[0]), "r"(a[1]), "r"(a[2]), "r"(a[3]), "r"(b0), "r"(b1));
}
__device__ __forceinline__ uint32_t smem_u32(const void* p) {
    uint32_t a;
    asm("{ .reg .u64 t; cvta.to.shared.u64 t, %1; cvt.u32.u64 %0, t; }"
        : "=r"(a) : "l"(p));
    return a;
}
__device__ __forceinline__ void cp16(uint32_t dst, const void* src) {
    asm volatile("cp.async.cg.shared.global [%0], [%1], 16;"
                 :: "r"(dst), "l"(src));
}
#define CP_COMMIT() asm volatile("cp.async.commit_group;" ::: "memory")
#define CP_WAIT(n)  asm volatile("cp.async.wait_group %0;" :: "n"(n) : "memory")
#define LDSM4(r, a)                                                         \
    asm volatile("ldmatrix.sync.aligned.m8n8.x4.shared.b16 "                \
                 "{%0,%1,%2,%3}, [%4];"                                     \
                 : "=r"((r)[0]), "=r"((r)[1]), "=r"((r)[2]), "=r"((r)[3])   \
                 : "r"(a))
#define LDSM4T(r, a)                                                        \
    asm volatile("ldmatrix.sync.aligned.m8n8.x4.trans.shared.b16 "          \
                 "{%0,%1,%2,%3}, [%4];"                                     \
                 : "=r"((r)[0]), "=r"((r)[1]), "=r"((r)[2]), "=r"((r)[3])   \
                 : "r"(a))
__device__ __forceinline__ uint32_t pack_h2(float lo, float hi) {
    __half2 h = __floats2half2_rn(lo, hi);
    return *(uint32_t*)&h;
}
__device__ __forceinline__ uint32_t h2exp2(uint32_t u) {
    uint32_t r;
    asm("ex2.approx.f16x2 %0, %1;" : "=r"(r) : "r"(u));
    return r;
}

// ---------------------------------------------------------------------------
// K_prep: blocks [0,2048): x fp32 -> half
//         blocks [2048,2304): scaled V-weights -> g_W
//         blocks [2304,2560): U weights -> g_Wu
// ---------------------------------------------------------------------------
__global__ __launch_bounds__(256) void k_prep(
    const float* __restrict__ x,
    const float* __restrict__ qU, const float* __restrict__ kU,
    const float* __restrict__ vU, const float* __restrict__ cU,
    const float* __restrict__ qV, const float* __restrict__ kV,
    const float* __restrict__ vV, const float* __restrict__ cV) {
    const int b = blockIdx.x, tid = threadIdx.x;
    if (b < 2048) {
        const int base = (b * 256 + tid) * 16;
        #pragma unroll
        for (int g = 0; g < 4; g++) {
            float4 v = *(const float4*)(x + base + g * 4);
            *(__half2*)(g_xh + base + g * 4)     = __floats2half2_rn(v.x, v.y);
            *(__half2*)(g_xh + base + g * 4 + 2) = __floats2half2_rn(v.z, v.w);
        }
    } else if (b < 2304) {
        const int bb = b - 2048;
        const int grp = bb >> 6, r = bb & 63;
        const float* Vsrc = (grp == 0) ? qV : (grp == 1) ? kV
                          : (grp == 2) ? vV : cV;
        float sc = powf((float)(r + 1), -0.7f);
        if (grp == 0) sc *= 0.125f * 1.4426950408889634f;
        const int c = tid * 4;
        float4 v = *(const float4*)(Vsrc + (size_t)r * 1024 + c);
        *(__half2*)(g_W + (size_t)bb * 1024 + c)     = __floats2half2_rn(v.x * sc, v.y * sc);
        *(__half2*)(g_W + (size_t)bb * 1024 + c + 2) = __floats2half2_rn(v.z * sc, v.w * sc);
    } else {
        const float* Us[4] = {qU, kU, vU, cU};
        const int base = (b - 2304) * 1024 + tid * 4;
        const int w = base >> 16, off = base & 65535;
        float4 u = *(const float4*)(Us[w] + off);
        *(__half2*)(g_Wu + base)     = __floats2half2_rn(u.x, u.y);
        *(__half2*)(g_Wu + base + 2) = __floats2half2_rn(u.z, u.w);
    }
}

// ---------------------------------------------------------------------------
// K1a: stage-1 qkv GEMM  P[m, n] = x[m,:1024] @ W[n,:1024]^T, NOUT=192.
// 128 threads/CTA, tile 32x192, grid 256. Warp: 32x48 = 12 chains.
// 3-stage cp.async pipeline over K-chunks of 32.
// ---------------------------------------------------------------------------
#define PADH1 40   // halfs; 80B row stride
__global__ __launch_bounds__(128) void k_g1a(const __half* __restrict__ A,
                                             __half* __restrict__ Pout) {
    extern __shared__ __half sg1h[];
    const int tid = threadIdx.x, w = tid >> 5, lane = tid & 31;
    const int quad = lane >> 2, qc = lane & 3;
    const int m0 = blockIdx.x * 32;
    constexpr int STRIDE = (32 + 192) * PADH1;   // halfs per stage

    auto stage = [&](int ch, int s) {
        const int k0 = ch * 32;
        __half* base = sg1h + s * STRIDE;
        #pragma unroll
        for (int i = tid; i < (32 + 192) * 4; i += 128) {
            int row = i >> 2, c8 = (i & 3) * 8;
            const __half* src = (row < 32)
                ? A   + (size_t)(m0 + row) * 1024 + k0 + c8
                : g_W + (size_t)(row - 32) * 1024 + k0 + c8;
            cp16(smem_u32(base + row * PADH1 + c8), src);
        }
    };

    float acc[2][6][4];
    #pragma unroll
    for (int mf = 0; mf < 2; mf++)
        #pragma unroll
        for (int nb = 0; nb < 6; nb++)
            #pragma unroll
            for (int i = 0; i < 4; i++) acc[mf][nb][i] = 0.f;

    stage(0, 0); CP_COMMIT();
    stage(1, 1); CP_COMMIT();

    for (int ch = 0; ch < 32; ch++) {
        if (ch + 2 < 32) stage(ch + 2, (ch + 2) % 3);
        CP_COMMIT();
        CP_WAIT(2);
        __syncthreads();
        const __half* Ab = sg1h + (ch % 3) * STRIDE;
        const __half* Bb = Ab + 32 * PADH1;
        #pragma unroll
        for (int kb = 0; kb < 2; kb++) {
            uint32_t a[2][4];
            #pragma unroll
            for (int mf = 0; mf < 2; mf++) {
                const __half* ap = Ab + (mf * 16 + quad) * PADH1
                                 + kb * 16 + 2 * qc;
                a[mf][0] = *(const uint32_t*)(ap);
                a[mf][1] = *(const uint32_t*)(ap + 8 * PADH1);
                a[mf][2] = *(const uint32_t*)(ap + 8);
                a[mf][3] = *(const uint32_t*)(ap + 8 * PADH1 + 8);
            }
            #pragma unroll
            for (int nb = 0; nb < 6; nb++) {
                const __half* bp = Bb + (w * 48 + nb * 8 + quad) * PADH1
                                 + kb * 16 + 2 * qc;
                uint32_t b0 = *(const uint32_t*)(bp);
                uint32_t b1 = *(const uint32_t*)(bp + 8);
                mma_f16(acc[0][nb], a[0], b0, b1);
                mma_f16(acc[1][nb], a[1], b0, b1);
            }
        }
        __syncthreads();
    }

    #pragma unroll
    for (int mf = 0; mf < 2; mf++) {
        const int row = m0 + mf * 16 + quad;
        #pragma unroll
        for (int nb = 0; nb < 6; nb++) {
            const int col = w * 48 + nb * 8 + 2 * qc;
            *(__half2*)(Pout + (size_t)row * 192 + col) =
                __floats2half2_rn(acc[mf][nb][0], acc[mf][nb][1]);
            *(__half2*)(Pout + (size_t)(row + 8) * 192 + col) =
                __floats2half2_rn(acc[mf][nb][2], acc[mf][nb][3]);
        }
    }
}

// ---------------------------------------------------------------------------
// K1b: stage-1 c-proj GEMM  P2[m,n] = Y[m,:1024] @ W[192+n,:1024]^T, NOUT=64
// 256 threads, tile 64x64, 3-stage cp.async.
// ---------------------------------------------------------------------------
__global__ __launch_bounds__(256) void k_g1b(__half* __restrict__ Pout) {
    extern __shared__ __half sg1bh[];
    const int tid = threadIdx.x, w = tid >> 5, lane = tid & 31;
    const int quad = lane >> 2, qc = lane & 3;
    const int wm = w & 1, wn = w >> 1;
    const int m0 = blockIdx.x * 64;
    constexpr int STRIDE = 128 * PADH1;
    const __half* Wp = g_W + (size_t)192 * 1024;

    auto stage = [&](int ch, int s) {
        const int k0 = ch * 32;
        __half* base = sg1bh + s * STRIDE;
        #pragma unroll
        for (int i = tid; i < 128 * 4; i += 256) {
            int row = i >> 2, c8 = (i & 3) * 8;
            const __half* src = (row < 64)
                ? g_Yh + (size_t)(m0 + row) * 1024 + k0 + c8
                : Wp   + (size_t)(row - 64) * 1024 + k0 + c8;
            cp16(smem_u32(base + row * PADH1 + c8), src);
        }
    };

    float acc[2][2][4] = {};
    stage(0, 0); CP_COMMIT();
    stage(1, 1); CP_COMMIT();

    for (int ch = 0; ch < 32; ch++) {
        if (ch + 2 < 32) stage(ch + 2, (ch + 2) % 3);
        CP_COMMIT();
        CP_WAIT(2);
        __syncthreads();
        const __half* Ab = sg1bh + (ch % 3) * STRIDE;
        const __half* Bb = Ab + 64 * PADH1;
        #pragma unroll
        for (int kb = 0; kb < 2; kb++) {
            uint32_t a[2][4];
            #pragma unroll
            for (int mf = 0; mf < 2; mf++) {
                const __half* ap = Ab + (wm * 32 + mf * 16 + quad) * PADH1
                                 + kb * 16 + 2 * qc;
                a[mf][0] = *(const uint32_t*)(ap);
                a[mf][1] = *(const uint32_t*)(ap + 8 * PADH1);
                a[mf][2] = *(const uint32_t*)(ap + 8);
                a[mf][3] = *(const uint32_t*)(ap + 8 * PADH1 + 8);
            }
            #pragma unroll
            for (int nb = 0; nb < 2; nb++) {
                const __half* bp = Bb + (wn * 16 + nb * 8 + quad) * PADH1
                                 + kb * 16 + 2 * qc;
                uint32_t b0 = *(const uint32_t*)(bp);
                uint32_t b1 = *(const uint32_t*)(bp + 8);
                mma_f16(acc[0][nb], a[0], b0, b1);
                mma_f16(acc[1][nb], a[1], b0, b1);
            }
        }
        __syncthreads();
    }

    #pragma unroll
    for (int mf = 0; mf < 2; mf++) {
        const int row = m0 + wm * 32 + mf * 16 + quad;
        #pragma unroll
        for (int nb = 0; nb < 2; nb++) {
            const int col = wn * 16 + nb * 8 + 2 * qc;
            *(__half2*)(Pout + (size_t)row * 64 + col) =
                __floats2half2_rn(acc[mf][nb][0], acc[mf][nb][1]);
            *(__half2*)(Pout + (size_t)(row + 8) * 64 + col) =
                __floats2half2_rn(acc[mf][nb][2], acc[mf][nb][3]);
        }
    }
}

// ---------------------------------------------------------------------------
// K2: stage-2 GEMM  y[m,n] = P[m,:64] @ U[n0+n,:64]^T   (non-persistent)
// M-tile 128 (8 warps x 16 rows), N-tile 128, K=64 single shot.
// mode 0: grid.z=3 -> q/k/v head-split half. mode 1: c-proj -> fp32 out.
// ---------------------------------------------------------------------------
#define PADH2 72   // halfs; 144B row stride
__global__ __launch_bounds__(256) void k_g2(const __half* __restrict__ Pbase,
                                            int ps,
                                            const __half* __restrict__ Wubase,
                                            int mode, float* __restrict__ outp) {
    extern __shared__ __half sg2h[];
    __half* As = sg2h;                 // [128][PADH2]
    __half* Bs = sg2h + 128 * PADH2;   // [128][PADH2]
    const int tid = threadIdx.x, w = tid >> 5, lane = tid & 31;
    const int quad = lane >> 2, qc = lane & 3;
    const int m0 = blockIdx.y * 128, n0 = blockIdx.x * 128;
    const int z = blockIdx.z;
    const __half* Pin = Pbase + (mode == 0 ? z * 64 : 0);
    const __half* Wu  = Wubase + (mode == 0 ? z * 65536 : 0);

    #pragma unroll
    for (int t = 0; t < 4; t++) {       // A: 1024 cp16
        int idx = tid + t * 256;
        int r = idx >> 3, c8 = (idx & 7) * 8;
        cp16(smem_u32(As + r * PADH2 + c8),
             Pin + (size_t)(m0 + r) * ps + c8);
    }
    #pragma unroll
    for (int t = 0; t < 4; t++) {       // B: 1024 cp16
        int idx = tid + t * 256;
        int n = idx >> 3, c8 = (idx & 7) * 8;
        cp16(smem_u32(Bs + n * PADH2 + c8),
             Wu + (size_t)(n0 + n) * 64 + c8);
    }
    CP_COMMIT();
    CP_WAIT(0);
    __syncthreads();

    float acc[16][4];
    #pragma unroll
    for (int nb = 0; nb < 16; nb++)
        #pragma unroll
        for (int i = 0; i < 4; i++) acc[nb][i] = 0.f;

    #pragma unroll
    for (int kb = 0; kb < 4; kb++) {
        uint32_t a[4];
        const __half* ap = As + (w * 16 + quad) * PADH2 + kb * 16 + 2 * qc;
        a[0] = *(const uint32_t*)(ap);
        a[1] = *(const uint32_t*)(ap + 8 * PADH2);
        a[2] = *(const uint32_t*)(ap + 8);
        a[3] = *(const uint32_t*)(ap + 8 * PADH2 + 8);
        #pragma unroll
        for (int nb = 0; nb < 16; nb++) {
            const __half* bp = Bs + (nb * 8 + quad) * PADH2 + kb * 16 + 2 * qc;
            mma_f16(acc[nb], a, *(const uint32_t*)(bp),
                    *(const uint32_t*)(bp + 8));
        }
    }

    const int row = m0 + w * 16 + quad;
    if (mode == 0) {
        __half* dst = (z == 0) ? g_Qh : (z == 1) ? g_Kh : g_Vh;
        const int b = row >> 11, t = row & (T_ - 1);
        #pragma unroll
        for (int nb = 0; nb < 16; nb++) {
            const int col = n0 + nb * 8 + 2 * qc;
            const int h = col >> 6, d = col & 63;
            __half* p0 = dst + (((size_t)(b * H_ + h) * T_ + t) * D_) + d;
            *(__half2*)p0 = __floats2half2_rn(acc[nb][0], acc[nb][1]);
            *(__half2*)(p0 + 8 * D_) = __floats2half2_rn(acc[nb][2], acc[nb][3]);
        }
    } else {
        #pragma unroll
        for (int nb = 0; nb < 16; nb++) {
            const int col = n0 + nb * 8 + 2 * qc;
            float* p0 = outp + (size_t)row * C_ + col;
            *(float2*)p0 = make_float2(acc[nb][0], acc[nb][1]);
            *(float2*)(p0 + 8 * C_) = make_float2(acc[nb][2], acc[nb][3]);
        }
    }
}

// ---------------------------------------------------------------------------
// K3: causal flash attention, fp16 mma + ldmatrix.
// 128 q-rows/CTA, 8 warps x 16 rows, 64-key tiles, cp.async double buffer.
// __launch_bounds__(256,2): 2 CTAs/SM -> 4 warps/SMSP.
// exp via ex2.approx.f16x2; row-sums via a CONSTANT ones b-fragment
// (b-frag lane cols n = quad => vones = quad==0 ? (1,1) : 0) — no LDSM.
// ---------------------------------------------------------------------------
#define PADA 72    // halfs; 144B stride
__global__ __launch_bounds__(256, 2) void k_attn() {
    extern __shared__ __half sah[];
    __half* Qs  = sah;                      // [128][PADA]
    __half* Ksb = sah + 128 * PADA;         // [2][64][PADA]
    __half* Vsb = Ksb + 2 * 64 * PADA;      // [2][64][PADA]
    const int tid = threadIdx.x, w = tid >> 5, lane = tid & 31;
    const int quad = lane >> 2, qc = lane & 3;
    const int msel = lane >> 3, rsel = lane & 7;
    const int mrow_a = (msel & 1) * 8 + rsel;   // Q / V(trans) row part
    const int mcol_a = (msel >> 1) * 8;
    const int mrow_b = (msel >> 1) * 8 + rsel;  // K row part
    const int mcol_b = (msel & 1) * 8;
    const int bh = blockIdx.y;
    const int qt = gridDim.x - 1 - blockIdx.x;  // heavy tiles first
    const int q0 = qt * 128;
    const __half* Qb = g_Qh + (size_t)bh * T_ * D_;
    const __half* Kb = g_Kh + (size_t)bh * T_ * D_;
    const __half* Vb = g_Vh + (size_t)bh * T_ * D_;
    const int nt = 2 * qt + 2;
    const uint32_t vones = (quad == 0) ? 0x3C003C00u : 0u;  // half2 (1,1)

    auto stage = [&](int j, int buf) {
        const __half* Kt = Kb + (size_t)j * 64 * D_;
        const __half* Vt = Vb + (size_t)j * 64 * D_;
        __half* Kd = Ksb + buf * 64 * PADA;
        __half* Vd = Vsb + buf * 64 * PADA;
        #pragma unroll
        for (int t = 0; t < 2; t++) {
            int idx = tid + t * 256;
            int r = idx >> 3, c8 = (idx & 7) * 8;
            cp16(smem_u32(Kd + r * PADA + c8), Kt + (size_t)r * D_ + c8);
            cp16(smem_u32(Vd + r * PADA + c8), Vt + (size_t)r * D_ + c8);
        }
    };

    // Q tile (128 rows) + first K/V tile
    #pragma unroll
    for (int t = 0; t < 4; t++) {
        int idx = tid + t * 256;
        int r = idx >> 3, c8 = (idx & 7) * 8;
        cp16(smem_u32(Qs + r * PADA + c8), Qb + (size_t)(q0 + r) * D_ + c8);
    }
    stage(0, 0);
    CP_COMMIT();

    uint32_t qa[4][4];
    float o[8][4] = {};
    float oS[4] = {};       // ones-frag accumulator: n=0 col = Sum(p)
    int buf = 0;

    for (int j = 0; j < nt; j++) {
        if (j + 1 < nt) { stage(j + 1, buf ^ 1); CP_COMMIT(); CP_WAIT(1); }
        else            { CP_WAIT(0); }
        __syncthreads();
        const __half* Ks = Ksb + buf * 64 * PADA;
        const __half* Vs = Vsb + buf * 64 * PADA;

        if (j == 0) {        // Q a-frags once
            #pragma unroll
            for (int kb = 0; kb < 4; kb++)
                LDSM4(qa[kb], smem_u32(Qs + (w * 16 + mrow_a) * PADA
                                       + kb * 16 + mcol_a));
        }

        // ---- S = Q @ K^T : 16x64 per warp ----
        float s[8][4];
        #pragma unroll
        for (int nb = 0; nb < 8; nb++)
            #pragma unroll
            for (int i = 0; i < 4; i++) s[nb][i] = 0.f;
        #pragma unroll
        for (int kb = 0; kb < 4; kb++)
            #pragma unroll
            for (int nbp = 0; nbp < 4; nbp++) {
                uint32_t bf[4];
                LDSM4(bf, smem_u32(Ks + (nbp * 16 + mrow_b) * PADA
                                   + kb * 16 + mcol_b));
                mma_f16(s[2 * nbp],     qa[kb], bf[0], bf[1]);
                mma_f16(s[2 * nbp + 1], qa[kb], bf[2], bf[3]);
            }

        // ---- causal mask on diagonal tiles ----
        if (j >= nt - 2) {
            const int rowrel0 = q0 + w * 16 + quad - 64 * j;
            #pragma unroll
            for (int nb = 0; nb < 8; nb++) {
                const int k0 = nb * 8 + 2 * qc;
                if (k0 > rowrel0)         s[nb][0] = -1e30f;
                if (k0 + 1 > rowrel0)     s[nb][1] = -1e30f;
                if (k0 > rowrel0 + 8)     s[nb][2] = -1e30f;
                if (k0 + 1 > rowrel0 + 8) s[nb][3] = -1e30f;
            }
        }

        // ---- P = 2^S in f16x2; O += P @ V; Sum(p) += P @ ones ----
        #pragma unroll
        for (int kb = 0; kb < 4; kb++) {
            uint32_t pa[4];
            pa[0] = h2exp2(pack_h2(s[2 * kb][0],     s[2 * kb][1]));
            pa[1] = h2exp2(pack_h2(s[2 * kb][2],     s[2 * kb][3]));
            pa[2] = h2exp2(pack_h2(s[2 * kb + 1][0], s[2 * kb + 1][1]));
            pa[3] = h2exp2(pack_h2(s[2 * kb + 1][2], s[2 * kb + 1][3]));
            #pragma unroll
            for (int nbp = 0; nbp < 4; nbp++) {
                uint32_t vf[4];
                LDSM4T(vf, smem_u32(Vs + (kb * 16 + mrow_a) * PADA
                                    + nbp * 16 + mcol_a));
                mma_f16(o[2 * nbp],     pa, vf[0], vf[1]);
                mma_f16(o[2 * nbp + 1], pa, vf[2], vf[3]);
            }
            mma_f16(oS, pa, vones, vones);   // constant ones b-frag
        }
        __syncthreads();
        buf ^= 1;
    }

    // ---- epilogue: Sum(p) lives at n=0 of the oS frag (qc==0 lanes) ----
    const int b = bh >> 4, h = bh & 15;
    const float l0 = __shfl_sync(0xffffffffu, oS[0], lane & 28);
    const float l1 = __shfl_sync(0xffffffffu, oS[2], lane & 28);
    const float inv0 = 1.f / l0, inv1 = 1.f / l1;
    const int r0 = q0 + w * 16 + quad;
    __half* y0 = g_Yh + ((size_t)b * T_ + r0) * C_ + h * 64;
    __half* y1 = y0 + 8 * C_;
    #pragma unroll
    for (int nb = 0; nb < 8; nb++) {
        const int c = nb * 8 + 2 * qc;
        *(__half2*)(y0 + c) = __floats2half2_rn(o[nb][0] * inv0,
                                                o[nb][1] * inv0);
        *(__half2*)(y1 + c) = __floats2half2_rn(o[nb][2] * inv1,
                                                o[nb][3] * inv1);
    }
}

// ---------------------------------------------------------------------------
extern "C" void kernel_launch(void* const* d_in, const int* in_sizes, int n_in,
                              void* d_out, int out_size) {
    (void)in_sizes; (void)n_in; (void)out_size;
    const float* x  = (const float*)d_in[0];
    const float* qU = (const float*)d_in[1];
    const float* qV = (const float*)d_in[2];
    const float* kU = (const float*)d_in[3];
    const float* kV = (const float*)d_in[4];
    const float* vU = (const float*)d_in[5];
    const float* vV = (const float*)d_in[6];
    const float* cU = (const float*)d_in[7];
    const float* cV = (const float*)d_in[8];
    float* out = (float*)d_out;

    const int sm_g1a = 3 * (32 + 192) * PADH1 * 2;              // 53760
    const int sm_g1b = 3 * 128 * PADH1 * 2;                     // 30720
    const int sm_g2  = 2 * 128 * PADH2 * 2;                     // 36864
    const int sm_att = (128 * PADA + 4 * 64 * PADA) * 2 + 512;  // 55808
    static int cfg_done = 0;
    if (!cfg_done) {
        cudaFuncSetAttribute(k_g1a,
            cudaFuncAttributeMaxDynamicSharedMemorySize, sm_g1a);
        cudaFuncSetAttribute(k_g1b,
            cudaFuncAttributeMaxDynamicSharedMemorySize, sm_g1b);
        cudaFuncSetAttribute(k_g2,
            cudaFuncAttributeMaxDynamicSharedMemorySize, sm_g2);
        cudaFuncSetAttribute(k_attn,
            cudaFuncAttributeMaxDynamicSharedMemorySize, sm_att);
        cfg_done = 1;
    }

    const dim3 g_qkv(C_ / 128, NT / 128, 3);   // 8 x 64 x 3
    const dim3 g_c(C_ / 128, NT / 128, 1);     // 8 x 64
    const dim3 g_att(T_ / 128, B_ * H_);       // 16 x 64

    __half* pXh; cudaGetSymbolAddress((void**)&pXh, g_xh);
    __half* pP;  cudaGetSymbolAddress((void**)&pP,  g_P);
    __half* pP2; cudaGetSymbolAddress((void**)&pP2, g_P2);
    __half* pWu; cudaGetSymbolAddress((void**)&pWu, g_Wu);

    k_prep<<<2560, 256>>>(x, qU, kU, vU, cU, qV, kV, vV, cV);      // 1
    k_g1a<<<NT / 32, 128, sm_g1a>>>(pXh, pP);                      // 2
    k_g2<<<g_qkv, 256, sm_g2>>>(pP, 192, pWu, 0, nullptr);         // 3
    k_attn<<<g_att, 256, sm_att>>>();                              // 4
    k_g1b<<<NT / 64, 256, sm_g1b>>>(pP2);                          // 5
    k_g2<<<g_c, 256, sm_g2>>>(pP2, 64, pWu + 3 * 65536, 1, out);   // 6
}

// round 12
// speedup vs baseline: 1.2572x; 1.1024x over previous
#include <cuda_runtime.h>
#include <cuda_fp16.h>
#include <cstdint>
#include <math.h>

#define B_ 4
#define T_ 2048
#define C_ 1024
#define H_ 16
#define D_ 64
#define R_ 64
#define NT 8192   // B*T

// ---------------- scratch (device globals; no allocation) ----------------
__device__ __half g_xh[NT * C_];      // x converted to half
__device__ __half g_W[256 * 1024];    // stacked scaled V-weights (half)
__device__ __half g_Wu[4 * 1024 * 64];// U weights (half)
__device__ __half g_P[NT * 192];      // rank-space P for q,k,v
__device__ __half g_P2[NT * 64];      // rank-space P for c-proj
__device__ __half g_Qh[NT * C_];      // [B,H,T,D], pre-scaled by 0.125*log2e
__device__ __half g_Kh[NT * C_];
__device__ __half g_Vh[NT * C_];
__device__ __half g_Yh[NT * C_];      // attention out [B,T,C]

// =================== portable tensor-core helpers (sm_80+) =================
__device__ __forceinline__ void mma_f16(float* d, const uint32_t* a,
                                        uint32_t b0, uint32_t b1) {
    asm volatile(
        "mma.sync.aligned.m16n8k16.row.col.f32.f16.f16.f32 "
        "{%0,%1,%2,%3}, {%4,%5,%6,%7}, {%8,%9}, {%0,%1,%2,%3};"
        : "+f"(d[0]), "+f"(d[1]), "+f"(d[2]), "+f"(d[3])
        : "r"(a[0]), "r"(a[1]), "r"(a[2]), "r"(a[3]), "r"(b0), "r"(b1));
}
__device__ __forceinline__ uint32_t smem_u32(const void* p) {
    uint32_t a;
    asm("{ .reg .u64 t; cvta.to.shared.u64 t, %1; cvt.u32.u64 %0, t; }"
        : "=r"(a) : "l"(p));
    return a;
}
__device__ __forceinline__ void cp16(uint32_t dst, const void* src) {
    asm volatile("cp.async.cg.shared.global [%0], [%1], 16;"
                 :: "r"(dst), "l"(src));
}
#define CP_COMMIT() asm volatile("cp.async.commit_group;" ::: "memory")
#define CP_WAIT(n)  asm volatile("cp.async.wait_group %0;" :: "n"(n) : "memory")
#define LDSM4(r, a)                                                         \
    asm volatile("ldmatrix.sync.aligned.m8n8.x4.shared.b16 "                \
                 "{%0,%1,%2,%3}, [%4];"                                     \
                 : "=r"((r)[0]), "=r"((r)[1]), "=r"((r)[2]), "=r"((r)[3])   \
                 : "r"(a))
#define LDSM4T(r, a)                                                        \
    asm volatile("ldmatrix.sync.aligned.m8n8.x4.trans.shared.b16 "          \
                 "{%0,%1,%2,%3}, [%4];"                                     \
                 : "=r"((r)[0]), "=r"((r)[1]), "=r"((r)[2]), "=r"((r)[3])   \
                 : "r"(a))
__device__ __forceinline__ uint32_t pack_h2(float lo, float hi) {
    __half2 h = __floats2half2_rn(lo, hi);
    return *(uint32_t*)&h;
}
__device__ __forceinline__ uint32_t h2exp2(uint32_t u) {
    uint32_t r;
    asm("ex2.approx.f16x2 %0, %1;" : "=r"(r) : "r"(u));
    return r;
}

// ---------------------------------------------------------------------------
// K_prep: blocks [0,2048): x fp32 -> half
//         blocks [2048,2304): scaled V-weights -> g_W
//         blocks [2304,2560): U weights -> g_Wu
// ---------------------------------------------------------------------------
__global__ __launch_bounds__(256) void k_prep(
    const float* __restrict__ x,
    const float* __restrict__ qU, const float* __restrict__ kU,
    const float* __restrict__ vU, const float* __restrict__ cU,
    const float* __restrict__ qV, const float* __restrict__ kV,
    const float* __restrict__ vV, const float* __restrict__ cV) {
    const int b = blockIdx.x, tid = threadIdx.x;
    if (b < 2048) {
        const int base = (b * 256 + tid) * 16;
        #pragma unroll
        for (int g = 0; g < 4; g++) {
            float4 v = *(const float4*)(x + base + g * 4);
            *(__half2*)(g_xh + base + g * 4)     = __floats2half2_rn(v.x, v.y);
            *(__half2*)(g_xh + base + g * 4 + 2) = __floats2half2_rn(v.z, v.w);
        }
    } else if (b < 2304) {
        const int bb = b - 2048;
        const int grp = bb >> 6, r = bb & 63;
        const float* Vsrc = (grp == 0) ? qV : (grp == 1) ? kV
                          : (grp == 2) ? vV : cV;
        float sc = powf((float)(r + 1), -0.7f);
        if (grp == 0) sc *= 0.125f * 1.4426950408889634f;
        const int c = tid * 4;
        float4 v = *(const float4*)(Vsrc + (size_t)r * 1024 + c);
        *(__half2*)(g_W + (size_t)bb * 1024 + c)     = __floats2half2_rn(v.x * sc, v.y * sc);
        *(__half2*)(g_W + (size_t)bb * 1024 + c + 2) = __floats2half2_rn(v.z * sc, v.w * sc);
    } else {
        const float* Us[4] = {qU, kU, vU, cU};
        const int base = (b - 2304) * 1024 + tid * 4;
        const int w = base >> 16, off = base & 65535;
        float4 u = *(const float4*)(Us[w] + off);
        *(__half2*)(g_Wu + base)     = __floats2half2_rn(u.x, u.y);
        *(__half2*)(g_Wu + base + 2) = __floats2half2_rn(u.z, u.w);
    }
}

// ---------------------------------------------------------------------------
// K1a: stage-1 qkv GEMM  P[m, n] = x[m,:1024] @ W[n,:1024]^T, NOUT=192.
// 128 threads/CTA, tile 32x192, grid 256. Warp: 32x48 = 12 chains.
// 3-stage cp.async pipeline, single __syncthreads per chunk.
// NOTE: CP_COMMIT is UNCONDITIONAL — CP_WAIT(1) only drains the oldest
// group when >=2 are pending; empty tail groups keep the ledger correct.
// ---------------------------------------------------------------------------
#define PADH1 40   // halfs; 80B row stride
__global__ __launch_bounds__(128) void k_g1a(const __half* __restrict__ A,
                                             __half* __restrict__ Pout) {
    extern __shared__ __half sg1h[];
    const int tid = threadIdx.x, w = tid >> 5, lane = tid & 31;
    const int quad = lane >> 2, qc = lane & 3;
    const int m0 = blockIdx.x * 32;
    constexpr int STRIDE = (32 + 192) * PADH1;   // halfs per stage
    const uint32_t sb = smem_u32(sg1h);

    auto stage = [&](int ch, int s) {
        const int k0 = ch * 32;
        const uint32_t base = sb + s * STRIDE * 2;
        #pragma unroll
        for (int i = tid; i < (32 + 192) * 4; i += 128) {
            int row = i >> 2, c8 = (i & 3) * 8;
            const __half* src = (row < 32)
                ? A   + (size_t)(m0 + row) * 1024 + k0 + c8
                : g_W + (size_t)(row - 32) * 1024 + k0 + c8;
            cp16(base + (row * PADH1 + c8) * 2, src);
        }
    };

    float acc[2][6][4];
    #pragma unroll
    for (int mf = 0; mf < 2; mf++)
        #pragma unroll
        for (int nb = 0; nb < 6; nb++)
            #pragma unroll
            for (int i = 0; i < 4; i++) acc[mf][nb][i] = 0.f;

    stage(0, 0); CP_COMMIT();
    stage(1, 1); CP_COMMIT();

    for (int ch = 0; ch < 32; ch++) {
        CP_WAIT(1);
        __syncthreads();
        if (ch + 2 < 32) stage(ch + 2, (ch + 2) % 3);
        CP_COMMIT();                      // unconditional (may be empty)
        const __half* Ab = sg1h + (ch % 3) * STRIDE;
        const __half* Bb = Ab + 32 * PADH1;
        #pragma unroll
        for (int kb = 0; kb < 2; kb++) {
            uint32_t a[2][4];
            #pragma unroll
            for (int mf = 0; mf < 2; mf++) {
                const __half* ap = Ab + (mf * 16 + quad) * PADH1
                                 + kb * 16 + 2 * qc;
                a[mf][0] = *(const uint32_t*)(ap);
                a[mf][1] = *(const uint32_t*)(ap + 8 * PADH1);
                a[mf][2] = *(const uint32_t*)(ap + 8);
                a[mf][3] = *(const uint32_t*)(ap + 8 * PADH1 + 8);
            }
            #pragma unroll
            for (int nb = 0; nb < 6; nb++) {
                const __half* bp = Bb + (w * 48 + nb * 8 + quad) * PADH1
                                 + kb * 16 + 2 * qc;
                uint32_t b0 = *(const uint32_t*)(bp);
                uint32_t b1 = *(const uint32_t*)(bp + 8);
                mma_f16(acc[0][nb], a[0], b0, b1);
                mma_f16(acc[1][nb], a[1], b0, b1);
            }
        }
    }

    #pragma unroll
    for (int mf = 0; mf < 2; mf++) {
        const int row = m0 + mf * 16 + quad;
        #pragma unroll
        for (int nb = 0; nb < 6; nb++) {
            const int col = w * 48 + nb * 8 + 2 * qc;
            *(__half2*)(Pout + (size_t)row * 192 + col) =
                __floats2half2_rn(acc[mf][nb][0], acc[mf][nb][1]);
            *(__half2*)(Pout + (size_t)(row + 8) * 192 + col) =
                __floats2half2_rn(acc[mf][nb][2], acc[mf][nb][3]);
        }
    }
}

// ---------------------------------------------------------------------------
// K1b: stage-1 c-proj GEMM  P2[m,n] = Y[m,:1024] @ W[192+n,:1024]^T, NOUT=64
// 256 threads, tile 64x64, 3-stage cp.async, single sync per chunk.
// ---------------------------------------------------------------------------
__global__ __launch_bounds__(256) void k_g1b(__half* __restrict__ Pout) {
    extern __shared__ __half sg1bh[];
    const int tid = threadIdx.x, w = tid >> 5, lane = tid & 31;
    const int quad = lane >> 2, qc = lane & 3;
    const int wm = w & 1, wn = w >> 1;
    const int m0 = blockIdx.x * 64;
    constexpr int STRIDE = 128 * PADH1;
    const __half* Wp = g_W + (size_t)192 * 1024;
    const uint32_t sb = smem_u32(sg1bh);

    auto stage = [&](int ch, int s) {
        const int k0 = ch * 32;
        const uint32_t base = sb + s * STRIDE * 2;
        #pragma unroll
        for (int i = tid; i < 128 * 4; i += 256) {
            int row = i >> 2, c8 = (i & 3) * 8;
            const __half* src = (row < 64)
                ? g_Yh + (size_t)(m0 + row) * 1024 + k0 + c8
                : Wp   + (size_t)(row - 64) * 1024 + k0 + c8;
            cp16(base + (row * PADH1 + c8) * 2, src);
        }
    };

    float acc[2][2][4] = {};
    stage(0, 0); CP_COMMIT();
    stage(1, 1); CP_COMMIT();

    for (int ch = 0; ch < 32; ch++) {
        CP_WAIT(1);
        __syncthreads();
        if (ch + 2 < 32) stage(ch + 2, (ch + 2) % 3);
        CP_COMMIT();                      // unconditional (may be empty)
        const __half* Ab = sg1bh + (ch % 3) * STRIDE;
        const __half* Bb = Ab + 64 * PADH1;
        #pragma unroll
        for (int kb = 0; kb < 2; kb++) {
            uint32_t a[2][4];
            #pragma unroll
            for (int mf = 0; mf < 2; mf++) {
                const __half* ap = Ab + (wm * 32 + mf * 16 + quad) * PADH1
                                 + kb * 16 + 2 * qc;
                a[mf][0] = *(const uint32_t*)(ap);
                a[mf][1] = *(const uint32_t*)(ap + 8 * PADH1);
                a[mf][2] = *(const uint32_t*)(ap + 8);
                a[mf][3] = *(const uint32_t*)(ap + 8 * PADH1 + 8);
            }
            #pragma unroll
            for (int nb = 0; nb < 2; nb++) {
                const __half* bp = Bb + (wn * 16 + nb * 8 + quad) * PADH1
                                 + kb * 16 + 2 * qc;
                uint32_t b0 = *(const uint32_t*)(bp);
                uint32_t b1 = *(const uint32_t*)(bp + 8);
                mma_f16(acc[0][nb], a[0], b0, b1);
                mma_f16(acc[1][nb], a[1], b0, b1);
            }
        }
    }

    #pragma unroll
    for (int mf = 0; mf < 2; mf++) {
        const int row = m0 + wm * 32 + mf * 16 + quad;
        #pragma unroll
        for (int nb = 0; nb < 2; nb++) {
            const int col = wn * 16 + nb * 8 + 2 * qc;
            *(__half2*)(Pout + (size_t)row * 64 + col) =
                __floats2half2_rn(acc[mf][nb][0], acc[mf][nb][1]);
            *(__half2*)(Pout + (size_t)(row + 8) * 64 + col) =
                __floats2half2_rn(acc[mf][nb][2], acc[mf][nb][3]);
        }
    }
}

// ---------------------------------------------------------------------------
// K2: stage-2 GEMM  y[m,n] = P[m,:64] @ U[n0+n,:64]^T   (non-persistent)
// M-tile 128 (8 warps x 16 rows), N-tile 128, K=64 single shot.
// ---------------------------------------------------------------------------
#define PADH2 72   // halfs; 144B row stride
__global__ __launch_bounds__(256) void k_g2(const __half* __restrict__ Pbase,
                                            int ps,
                                            const __half* __restrict__ Wubase,
                                            int mode, float* __restrict__ outp) {
    extern __shared__ __half sg2h[];
    __half* As = sg2h;                 // [128][PADH2]
    __half* Bs = sg2h + 128 * PADH2;   // [128][PADH2]
    const int tid = threadIdx.x, w = tid >> 5, lane = tid & 31;
    const int quad = lane >> 2, qc = lane & 3;
    const int m0 = blockIdx.y * 128, n0 = blockIdx.x * 128;
    const int z = blockIdx.z;
    const __half* Pin = Pbase + (mode == 0 ? z * 64 : 0);
    const __half* Wu  = Wubase + (mode == 0 ? z * 65536 : 0);
    const uint32_t sb = smem_u32(sg2h);

    #pragma unroll
    for (int t = 0; t < 4; t++) {       // A: 1024 cp16
        int idx = tid + t * 256;
        int r = idx >> 3, c8 = (idx & 7) * 8;
        cp16(sb + (r * PADH2 + c8) * 2, Pin + (size_t)(m0 + r) * ps + c8);
    }
    #pragma unroll
    for (int t = 0; t < 4; t++) {       // B: 1024 cp16
        int idx = tid + t * 256;
        int n = idx >> 3, c8 = (idx & 7) * 8;
        cp16(sb + (128 * PADH2 + n * PADH2 + c8) * 2,
             Wu + (size_t)(n0 + n) * 64 + c8);
    }
    CP_COMMIT();
    CP_WAIT(0);
    __syncthreads();

    float acc[16][4];
    #pragma unroll
    for (int nb = 0; nb < 16; nb++)
        #pragma unroll
        for (int i = 0; i < 4; i++) acc[nb][i] = 0.f;

    #pragma unroll
    for (int kb = 0; kb < 4; kb++) {
        uint32_t a[4];
        const __half* ap = As + (w * 16 + quad) * PADH2 + kb * 16 + 2 * qc;
        a[0] = *(const uint32_t*)(ap);
        a[1] = *(const uint32_t*)(ap + 8 * PADH2);
        a[2] = *(const uint32_t*)(ap + 8);
        a[3] = *(const uint32_t*)(ap + 8 * PADH2 + 8);
        #pragma unroll
        for (int nb = 0; nb < 16; nb++) {
            const __half* bp = Bs + (nb * 8 + quad) * PADH2 + kb * 16 + 2 * qc;
            mma_f16(acc[nb], a, *(const uint32_t*)(bp),
                    *(const uint32_t*)(bp + 8));
        }
    }

    const int row = m0 + w * 16 + quad;
    if (mode == 0) {
        __half* dst = (z == 0) ? g_Qh : (z == 1) ? g_Kh : g_Vh;
        const int b = row >> 11, t = row & (T_ - 1);
        #pragma unroll
        for (int nb = 0; nb < 16; nb++) {
            const int col = n0 + nb * 8 + 2 * qc;
            const int h = col >> 6, d = col & 63;
            __half* p0 = dst + (((size_t)(b * H_ + h) * T_ + t) * D_) + d;
            *(__half2*)p0 = __floats2half2_rn(acc[nb][0], acc[nb][1]);
            *(__half2*)(p0 + 8 * D_) = __floats2half2_rn(acc[nb][2], acc[nb][3]);
        }
    } else {
        #pragma unroll
        for (int nb = 0; nb < 16; nb++) {
            const int col = n0 + nb * 8 + 2 * qc;
            float* p0 = outp + (size_t)row * C_ + col;
            *(float2*)p0 = make_float2(acc[nb][0], acc[nb][1]);
            *(float2*)(p0 + 8 * C_) = make_float2(acc[nb][2], acc[nb][3]);
        }
    }
}

// ---------------------------------------------------------------------------
// K3: causal flash attention, fp16 mma + ldmatrix.
// 128 q-rows/CTA, 8 warps x 16 rows, 64-key tiles, cp.async double buffer,
// SINGLE __syncthreads per tile, all SMEM addresses precomputed as uint32.
// (Hazard audit: stage(j+1) writes buf (j+1)&1, last read by compute(j-1),
//  which is fenced by the barrier at the top of iteration j.)
// exp via ex2.approx.f16x2; row-sums via constant ones b-fragment.
// ---------------------------------------------------------------------------
#define PADA 72    // halfs; 144B stride
#define KVB (64 * PADA * 2)     // bytes per K/V buffer
__global__ __launch_bounds__(256, 2) void k_attn() {
    extern __shared__ __half sah[];
    const int tid = threadIdx.x, w = tid >> 5, lane = tid & 31;
    const int quad = lane >> 2, qc = lane & 3;
    const int msel = lane >> 3, rsel = lane & 7;
    const int mrow_a = (msel & 1) * 8 + rsel;   // Q / V(trans) row part
    const int mcol_a = (msel >> 1) * 8;
    const int mrow_b = (msel >> 1) * 8 + rsel;  // K row part
    const int mcol_b = (msel & 1) * 8;
    const int bh = blockIdx.y;
    const int qt = gridDim.x - 1 - blockIdx.x;  // heavy tiles first
    const int q0 = qt * 128;
    const __half* Qb = g_Qh + (size_t)bh * T_ * D_;
    const __half* Kb = g_Kh + (size_t)bh * T_ * D_;
    const __half* Vb = g_Vh + (size_t)bh * T_ * D_;
    const int nt = 2 * qt + 2;
    const uint32_t vones = (quad == 0) ? 0x3C003C00u : 0u;  // half2 (1,1)

    // ---- precomputed SMEM addresses (bytes) ----
    const uint32_t SB = smem_u32(sah);
    const uint32_t QS = SB;                    // Qs [128][PADA]
    const uint32_t KS = SB + 128 * PADA * 2;   // Ksb[2][64][PADA]
    const uint32_t VS = KS + 2 * KVB;          // Vsb[2][64][PADA]
    const uint32_t ka0 = KS + (mrow_b * PADA + mcol_b) * 2;
    const uint32_t va0 = VS + (mrow_a * PADA + mcol_a) * 2;
    // staging: thread covers rows r and r+32 at col c8
    const int r = tid >> 3, c8 = (tid & 7) * 8;
    const int gs0 = r * D_ + c8, gs1 = gs0 + 32 * D_;
    const uint32_t kst0 = KS + (r * PADA + c8) * 2;
    const uint32_t kst1 = kst0 + 32 * PADA * 2;
    const uint32_t vst0 = VS + (r * PADA + c8) * 2;
    const uint32_t vst1 = vst0 + 32 * PADA * 2;

    auto stage = [&](int j, int buf) {
        const __half* Kt = Kb + (size_t)j * 64 * D_;
        const __half* Vt = Vb + (size_t)j * 64 * D_;
        const uint32_t bo = buf * KVB;
        cp16(kst0 + bo, Kt + gs0);
        cp16(kst1 + bo, Kt + gs1);
        cp16(vst0 + bo, Vt + gs0);
        cp16(vst1 + bo, Vt + gs1);
    };

    // Q tile (128 rows) + first K/V tile
    #pragma unroll
    for (int t = 0; t < 4; t++) {
        const int row = r + t * 32;
        cp16(QS + (row * PADA + c8) * 2, Qb + (size_t)(q0 + row) * D_ + c8);
    }
    stage(0, 0);
    CP_COMMIT();
    CP_WAIT(0);
    __syncthreads();

    // Q a-frags (once)
    uint32_t qa[4][4];
    #pragma unroll
    for (int kb = 0; kb < 4; kb++)
        LDSM4(qa[kb], QS + ((w * 16 + mrow_a) * PADA + kb * 16 + mcol_a) * 2);

    float o[8][4] = {};
    float oS[4] = {};       // ones-frag accumulator: n=0 col = Sum(p)

    for (int j = 0; j < nt; j++) {
        if (j > 0) { CP_WAIT(0); __syncthreads(); }
        if (j + 1 < nt) { stage(j + 1, (j + 1) & 1); CP_COMMIT(); }
        const uint32_t kbase = ka0 + (j & 1) * KVB;
        const uint32_t vbase = va0 + (j & 1) * KVB;

        // ---- S = Q @ K^T : 16x64 per warp ----
        float s[8][4];
        #pragma unroll
        for (int nb = 0; nb < 8; nb++)
            #pragma unroll
            for (int i = 0; i < 4; i++) s[nb][i] = 0.f;
        #pragma unroll
        for (int kb = 0; kb < 4; kb++)
            #pragma unroll
            for (int nbp = 0; nbp < 4; nbp++) {
                uint32_t bf[4];
                LDSM4(bf, kbase + (nbp * 16 * PADA + kb * 16) * 2);
                mma_f16(s[2 * nbp],     qa[kb], bf[0], bf[1]);
                mma_f16(s[2 * nbp + 1], qa[kb], bf[2], bf[3]);
            }

        // ---- causal mask on diagonal tiles ----
        if (j >= nt - 2) {
            const int rowrel0 = q0 + w * 16 + quad - 64 * j;
            #pragma unroll
            for (int nb = 0; nb < 8; nb++) {
                const int k0 = nb * 8 + 2 * qc;
                if (k0 > rowrel0)         s[nb][0] = -1e30f;
                if (k0 + 1 > rowrel0)     s[nb][1] = -1e30f;
                if (k0 > rowrel0 + 8)     s[nb][2] = -1e30f;
                if (k0 + 1 > rowrel0 + 8) s[nb][3] = -1e30f;
            }
        }

        // ---- P = 2^S in f16x2; O += P @ V; Sum(p) += P @ ones ----
        #pragma unroll
        for (int kb = 0; kb < 4; kb++) {
            uint32_t pa[4];
            pa[0] = h2exp2(pack_h2(s[2 * kb][0],     s[2 * kb][1]));
            pa[1] = h2exp2(pack_h2(s[2 * kb][2],     s[2 * kb][3]));
            pa[2] = h2exp2(pack_h2(s[2 * kb + 1][0], s[2 * kb + 1][1]));
            pa[3] = h2exp2(pack_h2(s[2 * kb + 1][2], s[2 * kb + 1][3]));
            #pragma unroll
            for (int nbp = 0; nbp < 4; nbp++) {
                uint32_t vf[4];
                LDSM4T(vf, vbase + (kb * 16 * PADA + nbp * 16) * 2);
                mma_f16(o[2 * nbp],     pa, vf[0], vf[1]);
                mma_f16(o[2 * nbp + 1], pa, vf[2], vf[3]);
            }
            mma_f16(oS, pa, vones, vones);   // constant ones b-frag
        }
    }

    // ---- epilogue: Sum(p) at n=0 of oS frag (qc==0 lanes) ----
    const int b = bh >> 4, h = bh & 15;
    const float l0 = __shfl_sync(0xffffffffu, oS[0], lane & 28);
    const float l1 = __shfl_sync(0xffffffffu, oS[2], lane & 28);
    const float inv0 = 1.f / l0, inv1 = 1.f / l1;
    const int r0 = q0 + w * 16 + quad;
    __half* y0 = g_Yh + ((size_t)b * T_ + r0) * C_ + h * 64;
    __half* y1 = y0 + 8 * C_;
    #pragma unroll
    for (int nb = 0; nb < 8; nb++) {
        const int c = nb * 8 + 2 * qc;
        *(__half2*)(y0 + c) = __floats2half2_rn(o[nb][0] * inv0,
                                                o[nb][1] * inv0);
        *(__half2*)(y1 + c) = __floats2half2_rn(o[nb][2] * inv1,
                                                o[nb][3] * inv1);
    }
}

// ---------------------------------------------------------------------------
extern "C" void kernel_launch(void* const* d_in, const int* in_sizes, int n_in,
                              void* d_out, int out_size) {
    (void)in_sizes; (void)n_in; (void)out_size;
    const float* x  = (const float*)d_in[0];
    const float* qU = (const float*)d_in[1];
    const float* qV = (const float*)d_in[2];
    const float* kU = (const float*)d_in[3];
    const float* kV = (const float*)d_in[4];
    const float* vU = (const float*)d_in[5];
    const float* vV = (const float*)d_in[6];
    const float* cU = (const float*)d_in[7];
    const float* cV = (const float*)d_in[8];
    float* out = (float*)d_out;

    const int sm_g1a = 3 * (32 + 192) * PADH1 * 2;              // 53760
    const int sm_g1b = 3 * 128 * PADH1 * 2;                     // 30720
    const int sm_g2  = 2 * 128 * PADH2 * 2;                     // 36864
    const int sm_att = (128 * PADA + 4 * 64 * PADA) * 2;        // 55296
    static int cfg_done = 0;
    if (!cfg_done) {
        cudaFuncSetAttribute(k_g1a,
            cudaFuncAttributeMaxDynamicSharedMemorySize, sm_g1a);
        cudaFuncSetAttribute(k_g1b,
            cudaFuncAttributeMaxDynamicSharedMemorySize, sm_g1b);
        cudaFuncSetAttribute(k_g2,
            cudaFuncAttributeMaxDynamicSharedMemorySize, sm_g2);
        cudaFuncSetAttribute(k_attn,
            cudaFuncAttributeMaxDynamicSharedMemorySize, sm_att);
        cfg_done = 1;
    }

    const dim3 g_qkv(C_ / 128, NT / 128, 3);   // 8 x 64 x 3
    const dim3 g_c(C_ / 128, NT / 128, 1);     // 8 x 64
    const dim3 g_att(T_ / 128, B_ * H_);       // 16 x 64

    __half* pXh; cudaGetSymbolAddress((void**)&pXh, g_xh);
    __half* pP;  cudaGetSymbolAddress((void**)&pP,  g_P);
    __half* pP2; cudaGetSymbolAddress((void**)&pP2, g_P2);
    __half* pWu; cudaGetSymbolAddress((void**)&pWu, g_Wu);

    k_prep<<<2560, 256>>>(x, qU, kU, vU, cU, qV, kV, vV, cV);      // 1
    k_g1a<<<NT / 32, 128, sm_g1a>>>(pXh, pP);                      // 2
    k_g2<<<g_qkv, 256, sm_g2>>>(pP, 192, pWu, 0, nullptr);         // 3
    k_attn<<<g_att, 256, sm_att>>>();                              // 4
    k_g1b<<<NT / 64, 256, sm_g1b>>>(pP2);                          // 5
    k_g2<<<g_c, 256, sm_g2>>>(pP2, 64, pWu + 3 * 65536, 1, out);   // 6
}

// round 13
// speedup vs baseline: 1.2922x; 1.0278x over previous
#include <cuda_runtime.h>
#include <cuda_fp16.h>
#include <cstdint>
#include <math.h>

#define B_ 4
#define T_ 2048
#define C_ 1024
#define H_ 16
#define D_ 64
#define R_ 64
#define NT 8192   // B*T

// ---------------- scratch (device globals; no allocation) ----------------
__device__ __half g_xh[NT * C_];      // x converted to half
__device__ __half g_W[256 * 1024];    // stacked scaled V-weights (half)
__device__ __half g_Wu[4 * 1024 * 64];// U weights (half)
__device__ __half g_P[NT * 192];      // rank-space P for q,k,v
__device__ __half g_P2[NT * 64];      // rank-space P for c-proj
__device__ __half g_Qh[NT * C_];      // [B,H,T,D], pre-scaled by 0.125*log2e
__device__ __half g_Kh[NT * C_];
__device__ __half g_Vh[NT * C_];
__device__ __half g_Yh[NT * C_];      // attention out [B,T,C]

// =================== portable tensor-core helpers (sm_80+) =================
__device__ __forceinline__ void mma_f16(float* d, const uint32_t* a,
                                        uint32_t b0, uint32_t b1) {
    asm volatile(
        "mma.sync.aligned.m16n8k16.row.col.f32.f16.f16.f32 "
        "{%0,%1,%2,%3}, {%4,%5,%6,%7}, {%8,%9}, {%0,%1,%2,%3};"
        : "+f"(d[0]), "+f"(d[1]), "+f"(d[2]), "+f"(d[3])
        : "r"(a[0]), "r"(a[1]), "r"(a[2]), "r"(a[3]), "r"(b0), "r"(b1));
}
__device__ __forceinline__ uint32_t smem_u32(const void* p) {
    uint32_t a;
    asm("{ .reg .u64 t; cvta.to.shared.u64 t, %1; cvt.u32.u64 %0, t; }"
        : "=r"(a) : "l"(p));
    return a;
}
__device__ __forceinline__ void cp16(uint32_t dst, const void* src) {
    asm volatile("cp.async.cg.shared.global [%0], [%1], 16;"
                 :: "r"(dst), "l"(src));
}
#define CP_COMMIT() asm volatile("cp.async.commit_group;" ::: "memory")
#define CP_WAIT(n)  asm volatile("cp.async.wait_group %0;" :: "n"(n) : "memory")
#define LDSM4(r, a)                                                         \
    asm volatile("ldmatrix.sync.aligned.m8n8.x4.shared.b16 "                \
                 "{%0,%1,%2,%3}, [%4];"                                     \
                 : "=r"((r)[0]), "=r"((r)[1]), "=r"((r)[2]), "=r"((r)[3])   \
                 : "r"(a))
#define LDSM4T(r, a)                                                        \
    asm volatile("ldmatrix.sync.aligned.m8n8.x4.trans.shared.b16 "          \
                 "{%0,%1,%2,%3}, [%4];"                                     \
                 : "=r"((r)[0]), "=r"((r)[1]), "=r"((r)[2]), "=r"((r)[3])   \
                 : "r"(a))
__device__ __forceinline__ uint32_t pack_h2(float lo, float hi) {
    __half2 h = __floats2half2_rn(lo, hi);
    return *(uint32_t*)&h;
}
__device__ __forceinline__ uint32_t h2exp2(uint32_t u) {
    uint32_t r;
    asm("ex2.approx.f16x2 %0, %1;" : "=r"(r) : "r"(u));
    return r;
}

// ---------------------------------------------------------------------------
// K_prep: blocks [0,2048): x fp32 -> half
//         blocks [2048,2304): scaled V-weights -> g_W
//         blocks [2304,2560): U weights -> g_Wu
// ---------------------------------------------------------------------------
__global__ __launch_bounds__(256) void k_prep(
    const float* __restrict__ x,
    const float* __restrict__ qU, const float* __restrict__ kU,
    const float* __restrict__ vU, const float* __restrict__ cU,
    const float* __restrict__ qV, const float* __restrict__ kV,
    const float* __restrict__ vV, const float* __restrict__ cV) {
    const int b = blockIdx.x, tid = threadIdx.x;
    if (b < 2048) {
        const int base = (b * 256 + tid) * 16;
        #pragma unroll
        for (int g = 0; g < 4; g++) {
            float4 v = *(const float4*)(x + base + g * 4);
            *(__half2*)(g_xh + base + g * 4)     = __floats2half2_rn(v.x, v.y);
            *(__half2*)(g_xh + base + g * 4 + 2) = __floats2half2_rn(v.z, v.w);
        }
    } else if (b < 2304) {
        const int bb = b - 2048;
        const int grp = bb >> 6, r = bb & 63;
        const float* Vsrc = (grp == 0) ? qV : (grp == 1) ? kV
                          : (grp == 2) ? vV : cV;
        float sc = powf((float)(r + 1), -0.7f);
        if (grp == 0) sc *= 0.125f * 1.4426950408889634f;
        const int c = tid * 4;
        float4 v = *(const float4*)(Vsrc + (size_t)r * 1024 + c);
        *(__half2*)(g_W + (size_t)bb * 1024 + c)     = __floats2half2_rn(v.x * sc, v.y * sc);
        *(__half2*)(g_W + (size_t)bb * 1024 + c + 2) = __floats2half2_rn(v.z * sc, v.w * sc);
    } else {
        const float* Us[4] = {qU, kU, vU, cU};
        const int base = (b - 2304) * 1024 + tid * 4;
        const int w = base >> 16, off = base & 65535;
        float4 u = *(const float4*)(Us[w] + off);
        *(__half2*)(g_Wu + base)     = __floats2half2_rn(u.x, u.y);
        *(__half2*)(g_Wu + base + 2) = __floats2half2_rn(u.z, u.w);
    }
}

// ---------------------------------------------------------------------------
// K1a: stage-1 qkv GEMM  P[m, n] = x[m,:1024] @ W[n,:1024]^T, NOUT=192.
// 128 threads/CTA, tile 32x192, grid 256. Warp: 32x48 = 12 chains.
// 3-stage cp.async pipeline, single __syncthreads per chunk.
// CP_COMMIT unconditional (empty tail groups keep CP_WAIT ledger correct).
// ---------------------------------------------------------------------------
#define PADH1 40   // halfs; 80B row stride
__global__ __launch_bounds__(128) void k_g1a(const __half* __restrict__ A,
                                             __half* __restrict__ Pout) {
    extern __shared__ __half sg1h[];
    const int tid = threadIdx.x, w = tid >> 5, lane = tid & 31;
    const int quad = lane >> 2, qc = lane & 3;
    const int m0 = blockIdx.x * 32;
    constexpr int STRIDE = (32 + 192) * PADH1;   // halfs per stage
    const uint32_t sb = smem_u32(sg1h);

    auto stage = [&](int ch, int s) {
        const int k0 = ch * 32;
        const uint32_t base = sb + s * STRIDE * 2;
        #pragma unroll
        for (int i = tid; i < (32 + 192) * 4; i += 128) {
            int row = i >> 2, c8 = (i & 3) * 8;
            const __half* src = (row < 32)
                ? A   + (size_t)(m0 + row) * 1024 + k0 + c8
                : g_W + (size_t)(row - 32) * 1024 + k0 + c8;
            cp16(base + (row * PADH1 + c8) * 2, src);
        }
    };

    float acc[2][6][4];
    #pragma unroll
    for (int mf = 0; mf < 2; mf++)
        #pragma unroll
        for (int nb = 0; nb < 6; nb++)
            #pragma unroll
            for (int i = 0; i < 4; i++) acc[mf][nb][i] = 0.f;

    stage(0, 0); CP_COMMIT();
    stage(1, 1); CP_COMMIT();

    for (int ch = 0; ch < 32; ch++) {
        CP_WAIT(1);
        __syncthreads();
        if (ch + 2 < 32) stage(ch + 2, (ch + 2) % 3);
        CP_COMMIT();                      // unconditional (may be empty)
        const __half* Ab = sg1h + (ch % 3) * STRIDE;
        const __half* Bb = Ab + 32 * PADH1;
        #pragma unroll
        for (int kb = 0; kb < 2; kb++) {
            uint32_t a[2][4];
            #pragma unroll
            for (int mf = 0; mf < 2; mf++) {
                const __half* ap = Ab + (mf * 16 + quad) * PADH1
                                 + kb * 16 + 2 * qc;
                a[mf][0] = *(const uint32_t*)(ap);
                a[mf][1] = *(const uint32_t*)(ap + 8 * PADH1);
                a[mf][2] = *(const uint32_t*)(ap + 8);
                a[mf][3] = *(const uint32_t*)(ap + 8 * PADH1 + 8);
            }
            #pragma unroll
            for (int nb = 0; nb < 6; nb++) {
                const __half* bp = Bb + (w * 48 + nb * 8 + quad) * PADH1
                                 + kb * 16 + 2 * qc;
                uint32_t b0 = *(const uint32_t*)(bp);
                uint32_t b1 = *(const uint32_t*)(bp + 8);
                mma_f16(acc[0][nb], a[0], b0, b1);
                mma_f16(acc[1][nb], a[1], b0, b1);
            }
        }
    }

    #pragma unroll
    for (int mf = 0; mf < 2; mf++) {
        const int row = m0 + mf * 16 + quad;
        #pragma unroll
        for (int nb = 0; nb < 6; nb++) {
            const int col = w * 48 + nb * 8 + 2 * qc;
            *(__half2*)(Pout + (size_t)row * 192 + col) =
                __floats2half2_rn(acc[mf][nb][0], acc[mf][nb][1]);
            *(__half2*)(Pout + (size_t)(row + 8) * 192 + col) =
                __floats2half2_rn(acc[mf][nb][2], acc[mf][nb][3]);
        }
    }
}

// ---------------------------------------------------------------------------
// K1b: stage-1 c-proj GEMM  P2[m,n] = Y[m,:1024] @ W[192+n,:1024]^T, NOUT=64
// 256 threads, tile 64x64, 3-stage cp.async, single sync per chunk.
// ---------------------------------------------------------------------------
__global__ __launch_bounds__(256) void k_g1b(__half* __restrict__ Pout) {
    extern __shared__ __half sg1bh[];
    const int tid = threadIdx.x, w = tid >> 5, lane = tid & 31;
    const int quad = lane >> 2, qc = lane & 3;
    const int wm = w & 1, wn = w >> 1;
    const int m0 = blockIdx.x * 64;
    constexpr int STRIDE = 128 * PADH1;
    const __half* Wp = g_W + (size_t)192 * 1024;
    const uint32_t sb = smem_u32(sg1bh);

    auto stage = [&](int ch, int s) {
        const int k0 = ch * 32;
        const uint32_t base = sb + s * STRIDE * 2;
        #pragma unroll
        for (int i = tid; i < 128 * 4; i += 256) {
            int row = i >> 2, c8 = (i & 3) * 8;
            const __half* src = (row < 64)
                ? g_Yh + (size_t)(m0 + row) * 1024 + k0 + c8
                : Wp   + (size_t)(row - 64) * 1024 + k0 + c8;
            cp16(base + (row * PADH1 + c8) * 2, src);
        }
    };

    float acc[2][2][4] = {};
    stage(0, 0); CP_COMMIT();
    stage(1, 1); CP_COMMIT();

    for (int ch = 0; ch < 32; ch++) {
        CP_WAIT(1);
        __syncthreads();
        if (ch + 2 < 32) stage(ch + 2, (ch + 2) % 3);
        CP_COMMIT();                      // unconditional (may be empty)
        const __half* Ab = sg1bh + (ch % 3) * STRIDE;
        const __half* Bb = Ab + 64 * PADH1;
        #pragma unroll
        for (int kb = 0; kb < 2; kb++) {
            uint32_t a[2][4];
            #pragma unroll
            for (int mf = 0; mf < 2; mf++) {
                const __half* ap = Ab + (wm * 32 + mf * 16 + quad) * PADH1
                                 + kb * 16 + 2 * qc;
                a[mf][0] = *(const uint32_t*)(ap);
                a[mf][1] = *(const uint32_t*)(ap + 8 * PADH1);
                a[mf][2] = *(const uint32_t*)(ap + 8);
                a[mf][3] = *(const uint32_t*)(ap + 8 * PADH1 + 8);
            }
            #pragma unroll
            for (int nb = 0; nb < 2; nb++) {
                const __half* bp = Bb + (wn * 16 + nb * 8 + quad) * PADH1
                                 + kb * 16 + 2 * qc;
                uint32_t b0 = *(const uint32_t*)(bp);
                uint32_t b1 = *(const uint32_t*)(bp + 8);
                mma_f16(acc[0][nb], a[0], b0, b1);
                mma_f16(acc[1][nb], a[1], b0, b1);
            }
        }
    }

    #pragma unroll
    for (int mf = 0; mf < 2; mf++) {
        const int row = m0 + wm * 32 + mf * 16 + quad;
        #pragma unroll
        for (int nb = 0; nb < 2; nb++) {
            const int col = wn * 16 + nb * 8 + 2 * qc;
            *(__half2*)(Pout + (size_t)row * 64 + col) =
                __floats2half2_rn(acc[mf][nb][0], acc[mf][nb][1]);
            *(__half2*)(Pout + (size_t)(row + 8) * 64 + col) =
                __floats2half2_rn(acc[mf][nb][2], acc[mf][nb][3]);
        }
    }
}

// ---------------------------------------------------------------------------
// K2: stage-2 GEMM  y[m,n] = P[m,:64] @ U[n0+n,:64]^T   (non-persistent)
// M-tile 128 (8 warps x 16 rows), N-tile 128, K=64 single shot.
// ---------------------------------------------------------------------------
#define PADH2 72   // halfs; 144B row stride
__global__ __launch_bounds__(256) void k_g2(const __half* __restrict__ Pbase,
                                            int ps,
                                            const __half* __restrict__ Wubase,
                                            int mode, float* __restrict__ outp) {
    extern __shared__ __half sg2h[];
    __half* As = sg2h;                 // [128][PADH2]
    __half* Bs = sg2h + 128 * PADH2;   // [128][PADH2]
    const int tid = threadIdx.x, w = tid >> 5, lane = tid & 31;
    const int quad = lane >> 2, qc = lane & 3;
    const int m0 = blockIdx.y * 128, n0 = blockIdx.x * 128;
    const int z = blockIdx.z;
    const __half* Pin = Pbase + (mode == 0 ? z * 64 : 0);
    const __half* Wu  = Wubase + (mode == 0 ? z * 65536 : 0);
    const uint32_t sb = smem_u32(sg2h);

    #pragma unroll
    for (int t = 0; t < 4; t++) {       // A: 1024 cp16
        int idx = tid + t * 256;
        int r = idx >> 3, c8 = (idx & 7) * 8;
        cp16(sb + (r * PADH2 + c8) * 2, Pin + (size_t)(m0 + r) * ps + c8);
    }
    #pragma unroll
    for (int t = 0; t < 4; t++) {       // B: 1024 cp16
        int idx = tid + t * 256;
        int n = idx >> 3, c8 = (idx & 7) * 8;
        cp16(sb + (128 * PADH2 + n * PADH2 + c8) * 2,
             Wu + (size_t)(n0 + n) * 64 + c8);
    }
    CP_COMMIT();
    CP_WAIT(0);
    __syncthreads();

    float acc[16][4];
    #pragma unroll
    for (int nb = 0; nb < 16; nb++)
        #pragma unroll
        for (int i = 0; i < 4; i++) acc[nb][i] = 0.f;

    #pragma unroll
    for (int kb = 0; kb < 4; kb++) {
        uint32_t a[4];
        const __half* ap = As + (w * 16 + quad) * PADH2 + kb * 16 + 2 * qc;
        a[0] = *(const uint32_t*)(ap);
        a[1] = *(const uint32_t*)(ap + 8 * PADH2);
        a[2] = *(const uint32_t*)(ap + 8);
        a[3] = *(const uint32_t*)(ap + 8 * PADH2 + 8);
        #pragma unroll
        for (int nb = 0; nb < 16; nb++) {
            const __half* bp = Bs + (nb * 8 + quad) * PADH2 + kb * 16 + 2 * qc;
            mma_f16(acc[nb], a, *(const uint32_t*)(bp),
                    *(const uint32_t*)(bp + 8));
        }
    }

    const int row = m0 + w * 16 + quad;
    if (mode == 0) {
        __half* dst = (z == 0) ? g_Qh : (z == 1) ? g_Kh : g_Vh;
        const int b = row >> 11, t = row & (T_ - 1);
        #pragma unroll
        for (int nb = 0; nb < 16; nb++) {
            const int col = n0 + nb * 8 + 2 * qc;
            const int h = col >> 6, d = col & 63;
            __half* p0 = dst + (((size_t)(b * H_ + h) * T_ + t) * D_) + d;
            *(__half2*)p0 = __floats2half2_rn(acc[nb][0], acc[nb][1]);
            *(__half2*)(p0 + 8 * D_) = __floats2half2_rn(acc[nb][2], acc[nb][3]);
        }
    } else {
        #pragma unroll
        for (int nb = 0; nb < 16; nb++) {
            const int col = n0 + nb * 8 + 2 * qc;
            float* p0 = outp + (size_t)row * C_ + col;
            *(float2*)p0 = make_float2(acc[nb][0], acc[nb][1]);
            *(float2*)(p0 + 8 * C_) = make_float2(acc[nb][2], acc[nb][3]);
        }
    }
}

// ---------------------------------------------------------------------------
// K3: causal flash attention, fp16 mma + ldmatrix.
// 128 q-rows/CTA, 8 warps x 16 rows. PAIR-PROCESSED 64-key tiles with
// 4-deep K/V buffers: ONE __syncthreads per 2 tiles, warps drift across the
// pair so MUFU exp of one warp overlaps HMMA of another.
// (Hazards: stage(pair p+1) writes bufs (2p+2)&3,(2p+3)&3 = pair p-1's bufs,
//  last read before the barrier at top of iter p; compute(p) reads bufs
//  drained by this iteration's CP_WAIT(0).)  nt = 2qt+2 is always even.
// exp via ex2.approx.f16x2; row-sums via constant ones b-fragment.
// ---------------------------------------------------------------------------
#define PADA 72                   // halfs; 144B stride
#define KVB2 (64 * PADA * 2)      // bytes per single K or V tile buffer
__global__ __launch_bounds__(256, 2) void k_attn() {
    extern __shared__ __half sah[];
    const int tid = threadIdx.x, w = tid >> 5, lane = tid & 31;
    const int quad = lane >> 2, qc = lane & 3;
    const int msel = lane >> 3, rsel = lane & 7;
    const int mrow_a = (msel & 1) * 8 + rsel;   // Q / V(trans) row part
    const int mcol_a = (msel >> 1) * 8;
    const int mrow_b = (msel >> 1) * 8 + rsel;  // K row part
    const int mcol_b = (msel & 1) * 8;
    const int bh = blockIdx.y;
    const int qt = gridDim.x - 1 - blockIdx.x;  // heavy tiles first
    const int q0 = qt * 128;
    const __half* Qb = g_Qh + (size_t)bh * T_ * D_;
    const __half* Kb = g_Kh + (size_t)bh * T_ * D_;
    const __half* Vb = g_Vh + (size_t)bh * T_ * D_;
    const int nt = 2 * qt + 2;                  // even
    const int npair = qt + 1;
    const uint32_t vones = (quad == 0) ? 0x3C003C00u : 0u;  // half2 (1,1)

    // ---- precomputed SMEM addresses (bytes) ----
    const uint32_t SB = smem_u32(sah);
    const uint32_t QS = SB;                     // Qs [128][PADA]
    const uint32_t KS = SB + 128 * PADA * 2;    // Ksb[4][64][PADA]
    const uint32_t VS = KS + 4 * KVB2;          // Vsb[4][64][PADA]
    const uint32_t ka0 = KS + (mrow_b * PADA + mcol_b) * 2;
    const uint32_t va0 = VS + (mrow_a * PADA + mcol_a) * 2;
    // staging: thread covers rows r and r+32 at col c8
    const int r = tid >> 3, c8 = (tid & 7) * 8;
    const int gs0 = r * D_ + c8, gs1 = gs0 + 32 * D_;
    const uint32_t kst0 = KS + (r * PADA + c8) * 2;
    const uint32_t kst1 = kst0 + 32 * PADA * 2;
    const uint32_t vst0 = VS + (r * PADA + c8) * 2;
    const uint32_t vst1 = vst0 + 32 * PADA * 2;

    auto stage = [&](int j) {
        const __half* Kt = Kb + (size_t)j * 64 * D_;
        const __half* Vt = Vb + (size_t)j * 64 * D_;
        const uint32_t bo = (j & 3) * KVB2;
        cp16(kst0 + bo, Kt + gs0);
        cp16(kst1 + bo, Kt + gs1);
        cp16(vst0 + bo, Vt + gs0);
        cp16(vst1 + bo, Vt + gs1);
    };

    // Q tile (128 rows) + first pair, one commit group
    #pragma unroll
    for (int t = 0; t < 4; t++) {
        const int row = r + t * 32;
        cp16(QS + (row * PADA + c8) * 2, Qb + (size_t)(q0 + row) * D_ + c8);
    }
    stage(0);
    stage(1);
    CP_COMMIT();

    uint32_t qa[4][4];
    float o[8][4] = {};
    float oS[4] = {};       // ones-frag accumulator: n=0 col = Sum(p)

    auto compute = [&](int j, bool maskt) {
        const uint32_t kbase = ka0 + (j & 3) * KVB2;
        const uint32_t vbase = va0 + (j & 3) * KVB2;

        // S = Q @ K^T : 16x64 per warp
        float s[8][4];
        #pragma unroll
        for (int nb = 0; nb < 8; nb++)
            #pragma unroll
            for (int i = 0; i < 4; i++) s[nb][i] = 0.f;
        #pragma unroll
        for (int kb = 0; kb < 4; kb++)
            #pragma unroll
            for (int nbp = 0; nbp < 4; nbp++) {
                uint32_t bf[4];
                LDSM4(bf, kbase + (nbp * 16 * PADA + kb * 16) * 2);
                mma_f16(s[2 * nbp],     qa[kb], bf[0], bf[1]);
                mma_f16(s[2 * nbp + 1], qa[kb], bf[2], bf[3]);
            }

        // causal mask (final pair only; literal bool -> DCE in hot path)
        if (maskt) {
            const int rowrel0 = q0 + w * 16 + quad - 64 * j;
            #pragma unroll
            for (int nb = 0; nb < 8; nb++) {
                const int k0 = nb * 8 + 2 * qc;
                if (k0 > rowrel0)         s[nb][0] = -1e30f;
                if (k0 + 1 > rowrel0)     s[nb][1] = -1e30f;
                if (k0 > rowrel0 + 8)     s[nb][2] = -1e30f;
                if (k0 + 1 > rowrel0 + 8) s[nb][3] = -1e30f;
            }
        }

        // P = 2^S in f16x2; O += P @ V; Sum(p) += P @ ones
        #pragma unroll
        for (int kb = 0; kb < 4; kb++) {
            uint32_t pa[4];
            pa[0] = h2exp2(pack_h2(s[2 * kb][0],     s[2 * kb][1]));
            pa[1] = h2exp2(pack_h2(s[2 * kb][2],     s[2 * kb][3]));
            pa[2] = h2exp2(pack_h2(s[2 * kb + 1][0], s[2 * kb + 1][1]));
            pa[3] = h2exp2(pack_h2(s[2 * kb + 1][2], s[2 * kb + 1][3]));
            #pragma unroll
            for (int nbp = 0; nbp < 4; nbp++) {
                uint32_t vf[4];
                LDSM4T(vf, vbase + (kb * 16 * PADA + nbp * 16) * 2);
                mma_f16(o[2 * nbp],     pa, vf[0], vf[1]);
                mma_f16(o[2 * nbp + 1], pa, vf[2], vf[3]);
            }
            mma_f16(oS, pa, vones, vones);   // constant ones b-frag
        }
    };

    for (int p = 0; p < npair; p++) {
        CP_WAIT(0);
        __syncthreads();
        if (p == 0) {        // Q a-frags once (Q arrived with first group)
            #pragma unroll
            for (int kb = 0; kb < 4; kb++)
                LDSM4(qa[kb],
                      QS + ((w * 16 + mrow_a) * PADA + kb * 16 + mcol_a) * 2);
        }
        if (p + 1 < npair) {
            stage(2 * p + 2);
            stage(2 * p + 3);
            CP_COMMIT();
            compute(2 * p,     false);
            compute(2 * p + 1, false);
        } else {             // final pair carries the causal mask
            compute(2 * p,     true);
            compute(2 * p + 1, true);
        }
    }

    // ---- epilogue: Sum(p) at n=0 of oS frag (qc==0 lanes) ----
    const int b = bh >> 4, h = bh & 15;
    const float l0 = __shfl_sync(0xffffffffu, oS[0], lane & 28);
    const float l1 = __shfl_sync(0xffffffffu, oS[2], lane & 28);
    const float inv0 = 1.f / l0, inv1 = 1.f / l1;
    const int r0 = q0 + w * 16 + quad;
    __half* y0 = g_Yh + ((size_t)b * T_ + r0) * C_ + h * 64;
    __half* y1 = y0 + 8 * C_;
    #pragma unroll
    for (int nb = 0; nb < 8; nb++) {
        const int c = nb * 8 + 2 * qc;
        *(__half2*)(y0 + c) = __floats2half2_rn(o[nb][0] * inv0,
                                                o[nb][1] * inv0);
        *(__half2*)(y1 + c) = __floats2half2_rn(o[nb][2] * inv1,
                                                o[nb][3] * inv1);
    }
}

// ---------------------------------------------------------------------------
extern "C" void kernel_launch(void* const* d_in, const int* in_sizes, int n_in,
                              void* d_out, int out_size) {
    (void)in_sizes; (void)n_in; (void)out_size;
    const float* x  = (const float*)d_in[0];
    const float* qU = (const float*)d_in[1];
    const float* qV = (const float*)d_in[2];
    const float* kU = (const float*)d_in[3];
    const float* kV = (const float*)d_in[4];
    const float* vU = (const float*)d_in[5];
    const float* vV = (const float*)d_in[6];
    const float* cU = (const float*)d_in[7];
    const float* cV = (const float*)d_in[8];
    float* out = (float*)d_out;

    const int sm_g1a = 3 * (32 + 192) * PADH1 * 2;              // 53760
    const int sm_g1b = 3 * 128 * PADH1 * 2;                     // 30720
    const int sm_g2  = 2 * 128 * PADH2 * 2;                     // 36864
    const int sm_att = (128 * PADA + 8 * 64 * PADA) * 2;        // 92160
    static int cfg_done = 0;
    if (!cfg_done) {
        cudaFuncSetAttribute(k_g1a,
            cudaFuncAttributeMaxDynamicSharedMemorySize, sm_g1a);
        cudaFuncSetAttribute(k_g1b,
            cudaFuncAttributeMaxDynamicSharedMemorySize, sm_g1b);
        cudaFuncSetAttribute(k_g2,
            cudaFuncAttributeMaxDynamicSharedMemorySize, sm_g2);
        cudaFuncSetAttribute(k_attn,
            cudaFuncAttributeMaxDynamicSharedMemorySize, sm_att);
        cfg_done = 1;
    }

    const dim3 g_qkv(C_ / 128, NT / 128, 3);   // 8 x 64 x 3
    const dim3 g_c(C_ / 128, NT / 128, 1);     // 8 x 64
    const dim3 g_att(T_ / 128, B_ * H_);       // 16 x 64

    __half* pXh; cudaGetSymbolAddress((void**)&pXh, g_xh);
    __half* pP;  cudaGetSymbolAddress((void**)&pP,  g_P);
    __half* pP2; cudaGetSymbolAddress((void**)&pP2, g_P2);
    __half* pWu; cudaGetSymbolAddress((void**)&pWu, g_Wu);

    k_prep<<<2560, 256>>>(x, qU, kU, vU, cU, qV, kV, vV, cV);      // 1
    k_g1a<<<NT / 32, 128, sm_g1a>>>(pXh, pP);                      // 2
    k_g2<<<g_qkv, 256, sm_g2>>>(pP, 192, pWu, 0, nullptr);         // 3
    k_attn<<<g_att, 256, sm_att>>>();                              // 4
    k_g1b<<<NT / 64, 256, sm_g1b>>>(pP2);                          // 5
    k_g2<<<g_c, 256, sm_g2>>>(pP2, 64, pWu + 3 * 65536, 1, out);   // 6
}